// round 14
// baseline (speedup 1.0000x reference)
#include <cuda_runtime.h>
#include <cuda_bf16.h>
#include <cuda_fp16.h>
#include <cstdint>

#define S_LEN   2048
#define BATCH   2
#define DMODEL  1024
#define NHEAD   16
#define DKH     64
#define MTOT    (BATCH * S_LEN)
#define MWORDS  (S_LEN / 64)

// ---------------- scratch (static device globals) --------------------------
__device__ unsigned long long g_mbits[(size_t)BATCH * S_LEN * MWORDS];
// fp16 hi/lo splits of the three activation inputs (q,k,v)
__device__ __half g_Xh[3][(size_t)MTOT * DMODEL];
__device__ __half g_Xl[3][(size_t)MTOT * DMODEL];
// fp16 hi/lo splits of the four weight matrices (Wq,Wk,Wv,Wo)
__device__ __half g_Wh[4][(size_t)DMODEL * DMODEL];
__device__ __half g_Wl[4][(size_t)DMODEL * DMODEL];
// projected tensors
__device__ __half g_Qh[(size_t)MTOT * DMODEL];
__device__ __half g_Ql[(size_t)MTOT * DMODEL];
__device__ __half g_Kh[(size_t)MTOT * DMODEL];
__device__ __half g_Kl[(size_t)MTOT * DMODEL];
__device__ __half g_Vf[(size_t)MTOT * DMODEL];
// attention context (fp16 hi/lo)
__device__ __half g_Ch[(size_t)MTOT * DMODEL];
__device__ __half g_Cl[(size_t)MTOT * DMODEL];

// ---------------- helpers ---------------------------------------------------
__device__ __forceinline__ uint32_t smem_u32(const void* p) {
    uint32_t a;
    asm("{ .reg .u64 t; cvta.to.shared.u64 t, %1; cvt.u32.u64 %0, t; }"
        : "=r"(a) : "l"(p));
    return a;
}
__device__ __forceinline__ void ldsm4(uint32_t* r, uint32_t a) {
    asm volatile("ldmatrix.sync.aligned.m8n8.x4.shared.b16 {%0,%1,%2,%3}, [%4];"
                 : "=r"(r[0]), "=r"(r[1]), "=r"(r[2]), "=r"(r[3]) : "r"(a));
}
__device__ __forceinline__ void ldsm4t(uint32_t* r, uint32_t a) {
    asm volatile("ldmatrix.sync.aligned.m8n8.x4.trans.shared.b16 {%0,%1,%2,%3}, [%4];"
                 : "=r"(r[0]), "=r"(r[1]), "=r"(r[2]), "=r"(r[3]) : "r"(a));
}
__device__ __forceinline__ void mma16816h(float* d, const uint32_t* a,
                                          uint32_t b0, uint32_t b1) {
    asm volatile("mma.sync.aligned.m16n8k16.row.col.f32.f16.f16.f32 "
                 "{%0,%1,%2,%3}, {%4,%5,%6,%7}, {%8,%9}, {%0,%1,%2,%3};"
                 : "+f"(d[0]), "+f"(d[1]), "+f"(d[2]), "+f"(d[3])
                 : "r"(a[0]), "r"(a[1]), "r"(a[2]), "r"(a[3]), "r"(b0), "r"(b1));
}
__device__ __forceinline__ void cp16(uint32_t dst, const void* src) {
    asm volatile("cp.async.cg.shared.global [%0], [%1], 16;"
                 :: "r"(dst), "l"(src) : "memory");
}
__device__ __forceinline__ void cp_commit() {
    asm volatile("cp.async.commit_group;" ::: "memory");
}
template <int N> __device__ __forceinline__ void cp_wait() {
    asm volatile("cp.async.wait_group %0;" :: "n"(N) : "memory");
}
__device__ __forceinline__ uint32_t packh2(float a, float b) {
    __half2 h = __floats2half2_rn(a, b);
    return *reinterpret_cast<uint32_t*>(&h);
}
__device__ __forceinline__ void hsplit2(float a, float b, __half2& h, __half2& l) {
    h = __floats2half2_rn(a, b);
    float2 hf = __half22float2(h);
    l = __floats2half2_rn(a - hf.x, b - hf.y);
}

// ---------------- mask bit-packing -----------------------------------------
__global__ void pack_mask_kernel(const int* __restrict__ mask) {
    int gtid = blockIdx.x * blockDim.x + threadIdx.x;
    int w = gtid >> 5, lane = gtid & 31;
    int total_words = BATCH * S_LEN * MWORDS;
    if (w >= total_words) return;
    int row = w / MWORDS, j = w % MWORDS;
    size_t base = (size_t)row * S_LEN + (size_t)j * 64;
    unsigned b0 = __ballot_sync(0xffffffffu, mask[base + lane] != 0);
    unsigned b1 = __ballot_sync(0xffffffffu, mask[base + 32 + lane] != 0);
    if (lane == 0)
        g_mbits[w] = (unsigned long long)b0 | ((unsigned long long)b1 << 32);
}

// ---------------- batched fp32 -> fp16 hi/lo split --------------------------
__global__ __launch_bounds__(256) void cvt_split_batch(
    const float4* __restrict__ s0, const float4* __restrict__ s1,
    const float4* __restrict__ s2, const float4* __restrict__ s3,
    __half2* __restrict__ dh, __half2* __restrict__ dl,
    size_t stride_h2, int n4)
{
    int i = blockIdx.x * blockDim.x + threadIdx.x;
    if (i >= n4) return;
    int y = blockIdx.y;
    const float4* s = (y == 0) ? s0 : (y == 1) ? s1 : (y == 2) ? s2 : s3;
    float4 v = s[i];
    __half2 h0, l0, h1, l1;
    hsplit2(v.x, v.y, h0, l0);
    hsplit2(v.z, v.w, h1, l1);
    size_t o = (size_t)y * stride_h2 + 2 * (size_t)i;
    dh[o] = h0; dh[o + 1] = h1;
    dl[o] = l0; dl[o + 1] = l1;
}

// ---------------- mma.sync fp16x3 GEMM: Y = A @ B^T + bias ------------------
// CTA 128x128, 4 warps (2Mx2N), warp tile 64x64, K-chunk 32, double buffer.
// Fat warp tile cuts LDSM bytes per mma by 33% (crossbar co-bound fix).
#define ASTRIDE 80
#define ATILE   (128 * ASTRIDE)
#define GSTAGE  (4 * ATILE)
#define GEMM_SMEM (2 * GSTAGE)     // 81920

template <int MODE>   // 0: fp32 out; 1: fp16 hi/lo out; 2: fp16 out
__global__ __launch_bounds__(128, 2) void mma_gemm_kernel(
    const __half* __restrict__ Ahi, const __half* __restrict__ Alo,
    const __half* __restrict__ Bhi, const __half* __restrict__ Blo,
    const float* __restrict__ bias, float* __restrict__ Yf,
    __half2* __restrict__ Yhi, __half2* __restrict__ Ylo,
    __half2* __restrict__ Yh, int M, int N, int K)
{
    extern __shared__ char smem[];
    uint32_t sb = smem_u32(smem);
    int tid = threadIdx.x, lane = tid & 31, wid = tid >> 5;
    int bm = blockIdx.y * 128, bn = blockIdx.x * 128;
    int wmb = (wid >> 1) * 64, wnb = (wid & 1) * 64;

    float acc[4][8][4];
#pragma unroll
    for (int i = 0; i < 4; i++)
#pragma unroll
        for (int j = 0; j < 8; j++)
#pragma unroll
            for (int e = 0; e < 4; e++) acc[i][j][e] = 0.f;

    // stage = 4 tiles x 128 rows x 4 cu of 16B = 2048 units; 128 thr -> 16 iters
#define GEMM_LOAD(c, st)                                                        \
    {                                                                           \
        uint32_t base = sb + (st) * GSTAGE;                                     \
        _Pragma("unroll")                                                       \
        for (int t = 0; t < 16; t++) {                                          \
            int u = t * 128 + tid;                                              \
            int tile = u >> 9;                                                  \
            int row = (u >> 2) & 127, cu = u & 3;                               \
            uint32_t dst = base + tile * ATILE + row * ASTRIDE + cu * 16;       \
            const __half* s;                                                    \
            if (tile == 0)      s = Ahi + (size_t)(bm + row) * K + (c) * 32 + cu * 8; \
            else if (tile == 1) s = Alo + (size_t)(bm + row) * K + (c) * 32 + cu * 8; \
            else if (tile == 2) s = Bhi + (size_t)(bn + row) * K + (c) * 32 + cu * 8; \
            else                s = Blo + (size_t)(bn + row) * K + (c) * 32 + cu * 8; \
            cp16(dst, s);                                                       \
        }                                                                       \
    }

    GEMM_LOAD(0, 0);
    cp_commit();

    int nch = K / 32;
    for (int c = 0; c < nch; c++) {
        if (c + 1 < nch) { GEMM_LOAD(c + 1, (c + 1) & 1); cp_commit(); cp_wait<1>(); }
        else cp_wait<0>();
        __syncthreads();

        uint32_t sAh = sb + (c & 1) * GSTAGE;
        uint32_t sAl = sAh + ATILE, sBh = sAh + 2 * ATILE, sBl = sAh + 3 * ATILE;
#pragma unroll
        for (int ks = 0; ks < 2; ks++) {
            uint32_t ah[4][4], al[4][4];
#pragma unroll
            for (int i = 0; i < 4; i++) {
                int row = wmb + i * 16 + (lane & 15);
                int col = ks * 16 + ((lane & 16) ? 8 : 0);
                ldsm4(ah[i], sAh + row * ASTRIDE + col * 2);
                ldsm4(al[i], sAl + row * ASTRIDE + col * 2);
            }
#pragma unroll
            for (int jp = 0; jp < 2; jp++) {
                uint32_t bh[2][4], bl[2][4];
#pragma unroll
                for (int t = 0; t < 2; t++) {
                    int n = wnb + (2 * jp + t) * 16 + (lane & 7) + ((lane & 16) ? 8 : 0);
                    int col = ks * 16 + ((lane & 8) ? 8 : 0);
                    ldsm4(bh[t], sBh + n * ASTRIDE + col * 2);
                    ldsm4(bl[t], sBl + n * ASTRIDE + col * 2);
                }
                // term hh: 16 independent chains
#pragma unroll
                for (int i = 0; i < 4; i++)
#pragma unroll
                    for (int t = 0; t < 2; t++) {
                        mma16816h(acc[i][4 * jp + 2 * t],     ah[i], bh[t][0], bh[t][1]);
                        mma16816h(acc[i][4 * jp + 2 * t + 1], ah[i], bh[t][2], bh[t][3]);
                    }
                // term hl
#pragma unroll
                for (int i = 0; i < 4; i++)
#pragma unroll
                    for (int t = 0; t < 2; t++) {
                        mma16816h(acc[i][4 * jp + 2 * t],     ah[i], bl[t][0], bl[t][1]);
                        mma16816h(acc[i][4 * jp + 2 * t + 1], ah[i], bl[t][2], bl[t][3]);
                    }
                // term lh
#pragma unroll
                for (int i = 0; i < 4; i++)
#pragma unroll
                    for (int t = 0; t < 2; t++) {
                        mma16816h(acc[i][4 * jp + 2 * t],     al[i], bh[t][0], bh[t][1]);
                        mma16816h(acc[i][4 * jp + 2 * t + 1], al[i], bh[t][2], bh[t][3]);
                    }
            }
        }
        __syncthreads();
    }

#pragma unroll
    for (int i = 0; i < 4; i++) {
        int row = bm + wmb + i * 16 + (lane >> 2);
#pragma unroll
        for (int j = 0; j < 8; j++) {
            int col = bn + wnb + j * 8 + 2 * (lane & 3);
            float b0 = bias[col], b1 = bias[col + 1];
            float y0 = acc[i][j][0] + b0, y1 = acc[i][j][1] + b1;
            float y2 = acc[i][j][2] + b0, y3 = acc[i][j][3] + b1;
            size_t o0 = ((size_t)row * N + col);
            size_t o1 = ((size_t)(row + 8) * N + col);
            if (MODE == 0) {
                *(float2*)(Yf + o0) = make_float2(y0, y1);
                *(float2*)(Yf + o1) = make_float2(y2, y3);
            } else if (MODE == 1) {
                __half2 h, l;
                hsplit2(y0, y1, h, l);
                Yhi[o0 / 2] = h; Ylo[o0 / 2] = l;
                hsplit2(y2, y3, h, l);
                Yhi[o1 / 2] = h; Ylo[o1 / 2] = l;
            } else {
                Yh[o0 / 2] = __floats2half2_rn(y0, y1);
                Yh[o1 / 2] = __floats2half2_rn(y2, y3);
            }
        }
    }
}

// ---------------- mma.sync flash attention (all fp16) -----------------------
// CTA: 128 q-rows of one (b,h); 8 warps, warp = 16 q-rows; kv tiles of 64.
// QK: fp16 hi/lo x3 terms (term-major).  PV: single fp16 P x V.
#define QSTRIDE 144
#define QTILE   (128 * QSTRIDE)
#define KTILE   (64 * QSTRIDE)
#define KVSTAGE (3 * KTILE)                  // Kh, Kl, Vf
#define ATT_SMEM (2 * QTILE + 2 * KVSTAGE)   // 92160

__global__ __launch_bounds__(256) void mma_attn_kernel()
{
    extern __shared__ char smem[];
    uint32_t sb = smem_u32(smem);
    int tid = threadIdx.x, lane = tid & 31, wid = tid >> 5;
    int qb = blockIdx.x * 128, h = blockIdx.y, b = blockIdx.z;
    uint32_t sQh = sb, sQl = sb + QTILE, sKV = sb + 2 * QTILE;
    int wq = wid * 16;

    // Q tile load (hi + lo)
#pragma unroll
    for (int t = 0; t < 8; t++) {
        int half_ = t >> 2;
        int w = (t & 3) * 256 + tid;
        int row = w >> 3, cu = w & 7;
        const __half* s = (half_ ? g_Ql : g_Qh)
            + (size_t)(b * S_LEN + qb + row) * DMODEL + h * DKH + cu * 8;
        cp16(sb + half_ * QTILE + row * QSTRIDE + cu * 16, s);
    }
#define ATT_LOADKV(kt, st)                                                      \
    {                                                                           \
        uint32_t base = sKV + (st) * KVSTAGE;                                   \
        _Pragma("unroll")                                                       \
        for (int t = 0; t < 6; t++) {                                           \
            int tile = t >> 1;                                                  \
            int w = (t & 1) * 256 + tid;                                        \
            int row = w >> 3, cu = w & 7;                                       \
            size_t g = (size_t)(b * S_LEN + (kt) * 64 + row) * DMODEL + h * DKH + cu * 8; \
            const void* s;                                                      \
            if (tile == 0)      s = (const void*)(g_Kh + g);                    \
            else if (tile == 1) s = (const void*)(g_Kl + g);                    \
            else                s = (const void*)(g_Vf + g);                    \
            cp16(base + tile * KTILE + row * QSTRIDE + cu * 16, s);             \
        }                                                                       \
    }
    ATT_LOADKV(0, 0);
    cp_commit();

    float oacc[8][4];
#pragma unroll
    for (int j = 0; j < 8; j++)
#pragma unroll
        for (int e = 0; e < 4; e++) oacc[j][e] = 0.f;
    float mA = -1e30f, mB = -1e30f, lA = 0.f, lB = 0.f;

    int rA = qb + wq + (lane >> 2);
    const unsigned long long* mrowA = g_mbits + (size_t)(b * S_LEN + rA) * MWORDS;
    const unsigned long long* mrowB = mrowA + (size_t)8 * MWORDS;

    uint32_t qh[4][4], ql[4][4];

    for (int kt = 0; kt < 32; kt++) {
        if (kt + 1 < 32) { ATT_LOADKV(kt + 1, (kt + 1) & 1); cp_commit(); cp_wait<1>(); }
        else cp_wait<0>();
        __syncthreads();

        if (kt == 0) {
#pragma unroll
            for (int ks = 0; ks < 4; ks++) {
                int row = wq + (lane & 15);
                int col = ks * 16 + ((lane & 16) ? 8 : 0);
                ldsm4(qh[ks], sQh + row * QSTRIDE + col * 2);
                ldsm4(ql[ks], sQl + row * QSTRIDE + col * 2);
            }
        }
        uint32_t sKh = sKV + (kt & 1) * KVSTAGE;
        uint32_t sKl = sKh + KTILE, sVf = sKh + 2 * KTILE;

        // ---- scores S = (Qh+Ql)(Kh+Kl)^T, 3 fp16 terms, term-major ----
        float sacc[8][4];
#pragma unroll
        for (int j = 0; j < 8; j++)
#pragma unroll
            for (int e = 0; e < 4; e++) sacc[j][e] = 0.f;
#pragma unroll
        for (int ks = 0; ks < 4; ks++) {
#pragma unroll
            for (int jp = 0; jp < 2; jp++) {
                uint32_t kh[2][4], kl[2][4];
#pragma unroll
                for (int t = 0; t < 2; t++) {
                    int n = (2 * jp + t) * 16 + (lane & 7) + ((lane & 16) ? 8 : 0);
                    int col = ks * 16 + ((lane & 8) ? 8 : 0);
                    ldsm4(kh[t], sKh + n * QSTRIDE + col * 2);
                    ldsm4(kl[t], sKl + n * QSTRIDE + col * 2);
                }
#pragma unroll
                for (int t = 0; t < 2; t++) {       // term hh
                    mma16816h(sacc[4 * jp + 2 * t],     qh[ks], kh[t][0], kh[t][1]);
                    mma16816h(sacc[4 * jp + 2 * t + 1], qh[ks], kh[t][2], kh[t][3]);
                }
#pragma unroll
                for (int t = 0; t < 2; t++) {       // term hl
                    mma16816h(sacc[4 * jp + 2 * t],     qh[ks], kl[t][0], kl[t][1]);
                    mma16816h(sacc[4 * jp + 2 * t + 1], qh[ks], kl[t][2], kl[t][3]);
                }
#pragma unroll
                for (int t = 0; t < 2; t++) {       // term lh
                    mma16816h(sacc[4 * jp + 2 * t],     ql[ks], kh[t][0], kh[t][1]);
                    mma16816h(sacc[4 * jp + 2 * t + 1], ql[ks], kh[t][2], kh[t][3]);
                }
            }
        }

        // ---- masked online softmax ----
        unsigned long long mwA = mrowA[kt], mwB = mrowB[kt];
        float tmaxA = -1e30f, tmaxB = -1e30f;
#pragma unroll
        for (int j = 0; j < 8; j++) {
            int c0 = 8 * j + 2 * (lane & 3);
            sacc[j][0] = ((mwA >> c0) & 1ULL)       ? sacc[j][0] * 0.125f : -1e30f;
            sacc[j][1] = ((mwA >> (c0 + 1)) & 1ULL) ? sacc[j][1] * 0.125f : -1e30f;
            sacc[j][2] = ((mwB >> c0) & 1ULL)       ? sacc[j][2] * 0.125f : -1e30f;
            sacc[j][3] = ((mwB >> (c0 + 1)) & 1ULL) ? sacc[j][3] * 0.125f : -1e30f;
            tmaxA = fmaxf(tmaxA, fmaxf(sacc[j][0], sacc[j][1]));
            tmaxB = fmaxf(tmaxB, fmaxf(sacc[j][2], sacc[j][3]));
        }
        tmaxA = fmaxf(tmaxA, __shfl_xor_sync(0xffffffffu, tmaxA, 1));
        tmaxA = fmaxf(tmaxA, __shfl_xor_sync(0xffffffffu, tmaxA, 2));
        tmaxB = fmaxf(tmaxB, __shfl_xor_sync(0xffffffffu, tmaxB, 1));
        tmaxB = fmaxf(tmaxB, __shfl_xor_sync(0xffffffffu, tmaxB, 2));
        float nmA = fmaxf(mA, tmaxA), nmB = fmaxf(mB, tmaxB);
        float corrA = __expf(mA - nmA), corrB = __expf(mB - nmB);
        mA = nmA; mB = nmB;
        lA *= corrA; lB *= corrB;
#pragma unroll
        for (int j = 0; j < 8; j++) {
            oacc[j][0] *= corrA; oacc[j][1] *= corrA;
            oacc[j][2] *= corrB; oacc[j][3] *= corrB;
        }
        float psA = 0.f, psB = 0.f;
#pragma unroll
        for (int j = 0; j < 8; j++) {
            float p0 = (sacc[j][0] > -1e29f) ? __expf(sacc[j][0] - nmA) : 0.f;
            float p1 = (sacc[j][1] > -1e29f) ? __expf(sacc[j][1] - nmA) : 0.f;
            float p2 = (sacc[j][2] > -1e29f) ? __expf(sacc[j][2] - nmB) : 0.f;
            float p3 = (sacc[j][3] > -1e29f) ? __expf(sacc[j][3] - nmB) : 0.f;
            sacc[j][0] = p0; sacc[j][1] = p1; sacc[j][2] = p2; sacc[j][3] = p3;
            psA += p0 + p1; psB += p2 + p3;
        }
        psA += __shfl_xor_sync(0xffffffffu, psA, 1);
        psA += __shfl_xor_sync(0xffffffffu, psA, 2);
        psB += __shfl_xor_sync(0xffffffffu, psB, 1);
        psB += __shfl_xor_sync(0xffffffffu, psB, 2);
        lA += psA; lB += psB;

        // ---- PV: ctx += P(Vf), single fp16 term, term-major ----
#pragma unroll
        for (int ks = 0; ks < 4; ks++) {
            uint32_t pah[4];
            pah[0] = packh2(sacc[2 * ks][0],     sacc[2 * ks][1]);
            pah[1] = packh2(sacc[2 * ks][2],     sacc[2 * ks][3]);
            pah[2] = packh2(sacc[2 * ks + 1][0], sacc[2 * ks + 1][1]);
            pah[3] = packh2(sacc[2 * ks + 1][2], sacc[2 * ks + 1][3]);
#pragma unroll
            for (int dp = 0; dp < 2; dp++) {
                uint32_t vf[2][4];
#pragma unroll
                for (int t = 0; t < 2; t++) {
                    int kv = ks * 16 + (lane & 7) + ((lane & 8) ? 8 : 0);
                    int col = (2 * dp + t) * 16 + ((lane & 16) ? 8 : 0);
                    ldsm4t(vf[t], sVf + kv * QSTRIDE + col * 2);
                }
#pragma unroll
                for (int t = 0; t < 2; t++) {
                    mma16816h(oacc[4 * dp + 2 * t],     pah, vf[t][0], vf[t][1]);
                    mma16816h(oacc[4 * dp + 2 * t + 1], pah, vf[t][2], vf[t][3]);
                }
            }
        }
        __syncthreads();
    }

    // epilogue: normalize and write ctx directly as fp16 hi/lo
    float invA = (lA > 0.f) ? (1.f / lA) : 0.f;
    float invB = (lB > 0.f) ? (1.f / lB) : 0.f;
    size_t base0 = (size_t)(b * S_LEN + rA) * DMODEL + h * DKH;
    size_t base1 = base0 + (size_t)8 * DMODEL;
#pragma unroll
    for (int j = 0; j < 8; j++) {
        int col = 8 * j + 2 * (lane & 3);
        __half2 hh, ll;
        hsplit2(oacc[j][0] * invA, oacc[j][1] * invA, hh, ll);
        *(__half2*)(g_Ch + base0 + col) = hh;
        *(__half2*)(g_Cl + base0 + col) = ll;
        hsplit2(oacc[j][2] * invB, oacc[j][3] * invB, hh, ll);
        *(__half2*)(g_Ch + base1 + col) = hh;
        *(__half2*)(g_Cl + base1 + col) = ll;
    }
}

// ---------------- launch ----------------------------------------------------
extern "C" void kernel_launch(void* const* d_in, const int* in_sizes, int n_in,
                              void* d_out, int out_size) {
    const float* q    = (const float*)d_in[0];
    const float* k    = (const float*)d_in[1];
    const float* v    = (const float*)d_in[2];
    const int*   mask = (const int*)d_in[3];
    const float* Wq_b = (const float*)d_in[5];
    const float* Wk_b = (const float*)d_in[7];
    const float* Wv_b = (const float*)d_in[9];
    const float* Wo_b = (const float*)d_in[11];
    const float* Wq_w = (const float*)d_in[4];
    const float* Wk_w = (const float*)d_in[6];
    const float* Wv_w = (const float*)d_in[8];
    const float* Wo_w = (const float*)d_in[10];
    float* out = (float*)d_out;

    void *pXh, *pXl, *pWh, *pWl, *pQh, *pQl, *pKh, *pKl, *pVf, *pCh, *pCl;
    cudaGetSymbolAddress(&pXh, g_Xh);  cudaGetSymbolAddress(&pXl, g_Xl);
    cudaGetSymbolAddress(&pWh, g_Wh);  cudaGetSymbolAddress(&pWl, g_Wl);
    cudaGetSymbolAddress(&pQh, g_Qh);  cudaGetSymbolAddress(&pQl, g_Ql);
    cudaGetSymbolAddress(&pKh, g_Kh);  cudaGetSymbolAddress(&pKl, g_Kl);
    cudaGetSymbolAddress(&pVf, g_Vf);
    cudaGetSymbolAddress(&pCh, g_Ch);  cudaGetSymbolAddress(&pCl, g_Cl);

    cudaFuncSetAttribute(mma_gemm_kernel<0>,
                         cudaFuncAttributeMaxDynamicSharedMemorySize, GEMM_SMEM);
    cudaFuncSetAttribute(mma_gemm_kernel<1>,
                         cudaFuncAttributeMaxDynamicSharedMemorySize, GEMM_SMEM);
    cudaFuncSetAttribute(mma_gemm_kernel<2>,
                         cudaFuncAttributeMaxDynamicSharedMemorySize, GEMM_SMEM);
    cudaFuncSetAttribute(mma_attn_kernel,
                         cudaFuncAttributeMaxDynamicSharedMemorySize, ATT_SMEM);

    {
        int total_words = BATCH * S_LEN * MWORDS;
        int threads = total_words * 32;
        pack_mask_kernel<<<(threads + 255) / 256, 256>>>(mask);
    }

    const int nA4 = MTOT * DMODEL / 4;     // activation float4 count
    const int nW4 = DMODEL * DMODEL / 4;   // weight float4 count
    const size_t strideA = (size_t)MTOT * DMODEL / 2;   // __half2 units
    const size_t strideW = (size_t)DMODEL * DMODEL / 2;

    // split q,k,v (3-way batched) and Wq,Wk,Wv,Wo (4-way batched)
    cvt_split_batch<<<dim3((nA4 + 255) / 256, 3), 256>>>(
        (const float4*)q, (const float4*)k, (const float4*)v, (const float4*)v,
        (__half2*)pXh, (__half2*)pXl, strideA, nA4);
    cvt_split_batch<<<dim3((nW4 + 255) / 256, 4), 256>>>(
        (const float4*)Wq_w, (const float4*)Wk_w, (const float4*)Wv_w, (const float4*)Wo_w,
        (__half2*)pWh, (__half2*)pWl, strideW, nW4);

    dim3 gg(DMODEL / 128, MTOT / 128);
    const __half* Xh = (const __half*)pXh;
    const __half* Xl = (const __half*)pXl;
    const __half* Wh = (const __half*)pWh;
    const __half* Wl = (const __half*)pWl;
    const size_t aN = (size_t)MTOT * DMODEL;
    const size_t wN = (size_t)DMODEL * DMODEL;

    // Q projection -> fp16 hi/lo
    mma_gemm_kernel<1><<<gg, 128, GEMM_SMEM>>>(
        Xh, Xl, Wh, Wl, Wq_b,
        nullptr, (__half2*)pQh, (__half2*)pQl, nullptr, MTOT, DMODEL, DMODEL);
    // K projection -> fp16 hi/lo
    mma_gemm_kernel<1><<<gg, 128, GEMM_SMEM>>>(
        Xh + aN, Xl + aN, Wh + wN, Wl + wN, Wk_b,
        nullptr, (__half2*)pKh, (__half2*)pKl, nullptr, MTOT, DMODEL, DMODEL);
    // V projection -> fp16
    mma_gemm_kernel<2><<<gg, 128, GEMM_SMEM>>>(
        Xh + 2 * aN, Xl + 2 * aN, Wh + 2 * wN, Wl + 2 * wN, Wv_b,
        nullptr, nullptr, nullptr, (__half2*)pVf, MTOT, DMODEL, DMODEL);

    // attention -> ctx fp16 hi/lo
    mma_attn_kernel<<<dim3(S_LEN / 128, NHEAD, BATCH), 256, ATT_SMEM>>>();

    // O projection -> fp32 out
    mma_gemm_kernel<0><<<gg, 128, GEMM_SMEM>>>(
        (const __half*)pCh, (const __half*)pCl, Wh + 3 * wN, Wl + 3 * wN, Wo_b,
        out, nullptr, nullptr, nullptr, MTOT, DMODEL, DMODEL);
}

// round 15
// speedup vs baseline: 1.5074x; 1.5074x over previous
#include <cuda_runtime.h>
#include <cuda_bf16.h>
#include <cuda_fp16.h>
#include <cstdint>

#define S_LEN   2048
#define BATCH   2
#define DMODEL  1024
#define NHEAD   16
#define DKH     64
#define MTOT    (BATCH * S_LEN)
#define MWORDS  (S_LEN / 64)

// ---------------- scratch (static device globals) --------------------------
__device__ unsigned long long g_mbits[(size_t)BATCH * S_LEN * MWORDS];
__device__ __half g_Xh[3][(size_t)MTOT * DMODEL];
__device__ __half g_Xl[3][(size_t)MTOT * DMODEL];
__device__ __half g_Wh[4][(size_t)DMODEL * DMODEL];
__device__ __half g_Wl[4][(size_t)DMODEL * DMODEL];
__device__ __half g_Qh[(size_t)MTOT * DMODEL];
__device__ __half g_Ql[(size_t)MTOT * DMODEL];
__device__ __half g_Kh[(size_t)MTOT * DMODEL];
__device__ __half g_Kl[(size_t)MTOT * DMODEL];
__device__ __half g_Vf[(size_t)MTOT * DMODEL];
__device__ __half g_Ch[(size_t)MTOT * DMODEL];
__device__ __half g_Cl[(size_t)MTOT * DMODEL];

// ---------------- helpers ---------------------------------------------------
__device__ __forceinline__ uint32_t smem_u32(const void* p) {
    uint32_t a;
    asm("{ .reg .u64 t; cvta.to.shared.u64 t, %1; cvt.u32.u64 %0, t; }"
        : "=r"(a) : "l"(p));
    return a;
}
__device__ __forceinline__ void ldsm4(uint32_t* r, uint32_t a) {
    asm volatile("ldmatrix.sync.aligned.m8n8.x4.shared.b16 {%0,%1,%2,%3}, [%4];"
                 : "=r"(r[0]), "=r"(r[1]), "=r"(r[2]), "=r"(r[3]) : "r"(a));
}
__device__ __forceinline__ void ldsm4t(uint32_t* r, uint32_t a) {
    asm volatile("ldmatrix.sync.aligned.m8n8.x4.trans.shared.b16 {%0,%1,%2,%3}, [%4];"
                 : "=r"(r[0]), "=r"(r[1]), "=r"(r[2]), "=r"(r[3]) : "r"(a));
}
__device__ __forceinline__ void mma16816h(float* d, const uint32_t* a,
                                          uint32_t b0, uint32_t b1) {
    asm volatile("mma.sync.aligned.m16n8k16.row.col.f32.f16.f16.f32 "
                 "{%0,%1,%2,%3}, {%4,%5,%6,%7}, {%8,%9}, {%0,%1,%2,%3};"
                 : "+f"(d[0]), "+f"(d[1]), "+f"(d[2]), "+f"(d[3])
                 : "r"(a[0]), "r"(a[1]), "r"(a[2]), "r"(a[3]), "r"(b0), "r"(b1));
}
__device__ __forceinline__ void cp16(uint32_t dst, const void* src) {
    asm volatile("cp.async.cg.shared.global [%0], [%1], 16;"
                 :: "r"(dst), "l"(src) : "memory");
}
__device__ __forceinline__ void cp_commit() {
    asm volatile("cp.async.commit_group;" ::: "memory");
}
template <int N> __device__ __forceinline__ void cp_wait() {
    asm volatile("cp.async.wait_group %0;" :: "n"(N) : "memory");
}
__device__ __forceinline__ uint32_t packh2(float a, float b) {
    __half2 h = __floats2half2_rn(a, b);
    return *reinterpret_cast<uint32_t*>(&h);
}
__device__ __forceinline__ void hsplit2(float a, float b, __half2& h, __half2& l) {
    h = __floats2half2_rn(a, b);
    float2 hf = __half22float2(h);
    l = __floats2half2_rn(a - hf.x, b - hf.y);
}

// ---------------- mask bit-packing -----------------------------------------
__global__ void pack_mask_kernel(const int* __restrict__ mask) {
    int gtid = blockIdx.x * blockDim.x + threadIdx.x;
    int w = gtid >> 5, lane = gtid & 31;
    int total_words = BATCH * S_LEN * MWORDS;
    if (w >= total_words) return;
    int row = w / MWORDS, j = w % MWORDS;
    size_t base = (size_t)row * S_LEN + (size_t)j * 64;
    unsigned b0 = __ballot_sync(0xffffffffu, mask[base + lane] != 0);
    unsigned b1 = __ballot_sync(0xffffffffu, mask[base + 32 + lane] != 0);
    if (lane == 0)
        g_mbits[w] = (unsigned long long)b0 | ((unsigned long long)b1 << 32);
}

// ---------------- batched fp32 -> fp16 hi/lo split --------------------------
__global__ __launch_bounds__(256) void cvt_split_batch(
    const float4* __restrict__ s0, const float4* __restrict__ s1,
    const float4* __restrict__ s2, const float4* __restrict__ s3,
    __half2* __restrict__ dh, __half2* __restrict__ dl,
    size_t stride_h2, int n4)
{
    int i = blockIdx.x * blockDim.x + threadIdx.x;
    if (i >= n4) return;
    int y = blockIdx.y;
    const float4* s = (y == 0) ? s0 : (y == 1) ? s1 : (y == 2) ? s2 : s3;
    float4 v = s[i];
    __half2 h0, l0, h1, l1;
    hsplit2(v.x, v.y, h0, l0);
    hsplit2(v.z, v.w, h1, l1);
    size_t o = (size_t)y * stride_h2 + 2 * (size_t)i;
    dh[o] = h0; dh[o + 1] = h1;
    dl[o] = l0; dl[o + 1] = l1;
}

// ---------------- mma.sync fp16x3 GEMM: Y = A @ B^T + bias ------------------
// CTA 128x128, 8 warps (4Mx2N), warp tile 32x64, K-chunk 32, double buffer.
// (Proven best config: R7/R11 — 128 regs, 2 CTAs/SM, term-major ILP.)
#define ASTRIDE 80
#define ATILE   (128 * ASTRIDE)
#define GSTAGE  (4 * ATILE)
#define GEMM_SMEM (2 * GSTAGE)     // 81920

template <int MODE>   // 0: fp32 out; 1: fp16 hi/lo out; 2: fp16 out
__global__ __launch_bounds__(256, 2) void mma_gemm_kernel(
    const __half* __restrict__ Ahi, const __half* __restrict__ Alo,
    const __half* __restrict__ Bhi, const __half* __restrict__ Blo,
    const float* __restrict__ bias, float* __restrict__ Yf,
    __half2* __restrict__ Yhi, __half2* __restrict__ Ylo,
    __half2* __restrict__ Yh, int M, int N, int K)
{
    extern __shared__ char smem[];
    uint32_t sb = smem_u32(smem);
    int tid = threadIdx.x, lane = tid & 31, wid = tid >> 5;
    int bm = blockIdx.y * 128, bn = blockIdx.x * 128;
    int wmb = (wid >> 1) * 32, wnb = (wid & 1) * 64;

    float acc[2][8][4];
#pragma unroll
    for (int i = 0; i < 2; i++)
#pragma unroll
        for (int j = 0; j < 8; j++)
#pragma unroll
            for (int e = 0; e < 4; e++) acc[i][j][e] = 0.f;

#define GEMM_LOAD(c, st)                                                        \
    {                                                                           \
        uint32_t base = sb + (st) * GSTAGE;                                     \
        _Pragma("unroll")                                                       \
        for (int t = 0; t < 8; t++) {                                           \
            int tile = t >> 1;                                                  \
            int w = (t & 1) * 256 + tid;                                        \
            int row = w >> 2, cu = w & 3;                                       \
            uint32_t dst = base + tile * ATILE + row * ASTRIDE + cu * 16;       \
            const __half* s;                                                    \
            if (tile == 0)      s = Ahi + (size_t)(bm + row) * K + (c) * 32 + cu * 8; \
            else if (tile == 1) s = Alo + (size_t)(bm + row) * K + (c) * 32 + cu * 8; \
            else if (tile == 2) s = Bhi + (size_t)(bn + row) * K + (c) * 32 + cu * 8; \
            else                s = Blo + (size_t)(bn + row) * K + (c) * 32 + cu * 8; \
            cp16(dst, s);                                                       \
        }                                                                       \
    }

    GEMM_LOAD(0, 0);
    cp_commit();

    int nch = K / 32;
    for (int c = 0; c < nch; c++) {
        if (c + 1 < nch) { GEMM_LOAD(c + 1, (c + 1) & 1); cp_commit(); cp_wait<1>(); }
        else cp_wait<0>();
        __syncthreads();

        uint32_t sAh = sb + (c & 1) * GSTAGE;
        uint32_t sAl = sAh + ATILE, sBh = sAh + 2 * ATILE, sBl = sAh + 3 * ATILE;
#pragma unroll
        for (int ks = 0; ks < 2; ks++) {
            uint32_t ah[2][4], al[2][4];
#pragma unroll
            for (int i = 0; i < 2; i++) {
                int row = wmb + i * 16 + (lane & 15);
                int col = ks * 16 + ((lane & 16) ? 8 : 0);
                ldsm4(ah[i], sAh + row * ASTRIDE + col * 2);
                ldsm4(al[i], sAl + row * ASTRIDE + col * 2);
            }
#pragma unroll
            for (int jp = 0; jp < 2; jp++) {
                uint32_t bh[2][4], bl[2][4];
#pragma unroll
                for (int t = 0; t < 2; t++) {
                    int n = wnb + (2 * jp + t) * 16 + (lane & 7) + ((lane & 16) ? 8 : 0);
                    int col = ks * 16 + ((lane & 8) ? 8 : 0);
                    ldsm4(bh[t], sBh + n * ASTRIDE + col * 2);
                    ldsm4(bl[t], sBl + n * ASTRIDE + col * 2);
                }
                // term hh
#pragma unroll
                for (int i = 0; i < 2; i++)
#pragma unroll
                    for (int t = 0; t < 2; t++) {
                        mma16816h(acc[i][4 * jp + 2 * t],     ah[i], bh[t][0], bh[t][1]);
                        mma16816h(acc[i][4 * jp + 2 * t + 1], ah[i], bh[t][2], bh[t][3]);
                    }
                // term hl
#pragma unroll
                for (int i = 0; i < 2; i++)
#pragma unroll
                    for (int t = 0; t < 2; t++) {
                        mma16816h(acc[i][4 * jp + 2 * t],     ah[i], bl[t][0], bl[t][1]);
                        mma16816h(acc[i][4 * jp + 2 * t + 1], ah[i], bl[t][2], bl[t][3]);
                    }
                // term lh
#pragma unroll
                for (int i = 0; i < 2; i++)
#pragma unroll
                    for (int t = 0; t < 2; t++) {
                        mma16816h(acc[i][4 * jp + 2 * t],     al[i], bh[t][0], bh[t][1]);
                        mma16816h(acc[i][4 * jp + 2 * t + 1], al[i], bh[t][2], bh[t][3]);
                    }
            }
        }
        __syncthreads();
    }

#pragma unroll
    for (int i = 0; i < 2; i++) {
        int row = bm + wmb + i * 16 + (lane >> 2);
#pragma unroll
        for (int j = 0; j < 8; j++) {
            int col = bn + wnb + j * 8 + 2 * (lane & 3);
            float b0 = bias[col], b1 = bias[col + 1];
            float y0 = acc[i][j][0] + b0, y1 = acc[i][j][1] + b1;
            float y2 = acc[i][j][2] + b0, y3 = acc[i][j][3] + b1;
            size_t o0 = ((size_t)row * N + col);
            size_t o1 = ((size_t)(row + 8) * N + col);
            if (MODE == 0) {
                *(float2*)(Yf + o0) = make_float2(y0, y1);
                *(float2*)(Yf + o1) = make_float2(y2, y3);
            } else if (MODE == 1) {
                __half2 h, l;
                hsplit2(y0, y1, h, l);
                Yhi[o0 / 2] = h; Ylo[o0 / 2] = l;
                hsplit2(y2, y3, h, l);
                Yhi[o1 / 2] = h; Ylo[o1 / 2] = l;
            } else {
                Yh[o0 / 2] = __floats2half2_rn(y0, y1);
                Yh[o1 / 2] = __floats2half2_rn(y2, y3);
            }
        }
    }
}

// ---------------- mma.sync flash attention (all fp16) -----------------------
// CTA: 128 q-rows of one (b,h); 8 warps, warp = 16 q-rows; kv tiles of 64.
// QK: fp16 hi/lo x3 terms (term-major).  PV: single fp16 P x V.
#define QSTRIDE 144
#define QTILE   (128 * QSTRIDE)
#define KTILE   (64 * QSTRIDE)
#define KVSTAGE (3 * KTILE)                  // Kh, Kl, Vf
#define ATT_SMEM (2 * QTILE + 2 * KVSTAGE)   // 92160

__global__ __launch_bounds__(256) void mma_attn_kernel()
{
    extern __shared__ char smem[];
    uint32_t sb = smem_u32(smem);
    int tid = threadIdx.x, lane = tid & 31, wid = tid >> 5;
    int qb = blockIdx.x * 128, h = blockIdx.y, b = blockIdx.z;
    uint32_t sQh = sb, sQl = sb + QTILE, sKV = sb + 2 * QTILE;
    int wq = wid * 16;

    // Q tile load (hi + lo)
#pragma unroll
    for (int t = 0; t < 8; t++) {
        int half_ = t >> 2;
        int w = (t & 3) * 256 + tid;
        int row = w >> 3, cu = w & 7;
        const __half* s = (half_ ? g_Ql : g_Qh)
            + (size_t)(b * S_LEN + qb + row) * DMODEL + h * DKH + cu * 8;
        cp16(sb + half_ * QTILE + row * QSTRIDE + cu * 16, s);
    }
#define ATT_LOADKV(kt, st)                                                      \
    {                                                                           \
        uint32_t base = sKV + (st) * KVSTAGE;                                   \
        _Pragma("unroll")                                                       \
        for (int t = 0; t < 6; t++) {                                           \
            int tile = t >> 1;                                                  \
            int w = (t & 1) * 256 + tid;                                        \
            int row = w >> 3, cu = w & 7;                                       \
            size_t g = (size_t)(b * S_LEN + (kt) * 64 + row) * DMODEL + h * DKH + cu * 8; \
            const void* s;                                                      \
            if (tile == 0)      s = (const void*)(g_Kh + g);                    \
            else if (tile == 1) s = (const void*)(g_Kl + g);                    \
            else                s = (const void*)(g_Vf + g);                    \
            cp16(base + tile * KTILE + row * QSTRIDE + cu * 16, s);             \
        }                                                                       \
    }
    ATT_LOADKV(0, 0);
    cp_commit();

    float oacc[8][4];
#pragma unroll
    for (int j = 0; j < 8; j++)
#pragma unroll
        for (int e = 0; e < 4; e++) oacc[j][e] = 0.f;
    float mA = -1e30f, mB = -1e30f, lA = 0.f, lB = 0.f;

    int rA = qb + wq + (lane >> 2);
    const unsigned long long* mrowA = g_mbits + (size_t)(b * S_LEN + rA) * MWORDS;
    const unsigned long long* mrowB = mrowA + (size_t)8 * MWORDS;

    uint32_t qh[4][4], ql[4][4];

    for (int kt = 0; kt < 32; kt++) {
        if (kt + 1 < 32) { ATT_LOADKV(kt + 1, (kt + 1) & 1); cp_commit(); cp_wait<1>(); }
        else cp_wait<0>();
        __syncthreads();

        if (kt == 0) {
#pragma unroll
            for (int ks = 0; ks < 4; ks++) {
                int row = wq + (lane & 15);
                int col = ks * 16 + ((lane & 16) ? 8 : 0);
                ldsm4(qh[ks], sQh + row * QSTRIDE + col * 2);
                ldsm4(ql[ks], sQl + row * QSTRIDE + col * 2);
            }
        }
        uint32_t sKh = sKV + (kt & 1) * KVSTAGE;
        uint32_t sKl = sKh + KTILE, sVf = sKh + 2 * KTILE;

        // ---- scores S = (Qh+Ql)(Kh+Kl)^T, 3 fp16 terms, term-major ----
        float sacc[8][4];
#pragma unroll
        for (int j = 0; j < 8; j++)
#pragma unroll
            for (int e = 0; e < 4; e++) sacc[j][e] = 0.f;
#pragma unroll
        for (int ks = 0; ks < 4; ks++) {
#pragma unroll
            for (int jp = 0; jp < 2; jp++) {
                uint32_t kh[2][4], kl[2][4];
#pragma unroll
                for (int t = 0; t < 2; t++) {
                    int n = (2 * jp + t) * 16 + (lane & 7) + ((lane & 16) ? 8 : 0);
                    int col = ks * 16 + ((lane & 8) ? 8 : 0);
                    ldsm4(kh[t], sKh + n * QSTRIDE + col * 2);
                    ldsm4(kl[t], sKl + n * QSTRIDE + col * 2);
                }
#pragma unroll
                for (int t = 0; t < 2; t++) {       // term hh
                    mma16816h(sacc[4 * jp + 2 * t],     qh[ks], kh[t][0], kh[t][1]);
                    mma16816h(sacc[4 * jp + 2 * t + 1], qh[ks], kh[t][2], kh[t][3]);
                }
#pragma unroll
                for (int t = 0; t < 2; t++) {       // term hl
                    mma16816h(sacc[4 * jp + 2 * t],     qh[ks], kl[t][0], kl[t][1]);
                    mma16816h(sacc[4 * jp + 2 * t + 1], qh[ks], kl[t][2], kl[t][3]);
                }
#pragma unroll
                for (int t = 0; t < 2; t++) {       // term lh
                    mma16816h(sacc[4 * jp + 2 * t],     ql[ks], kh[t][0], kh[t][1]);
                    mma16816h(sacc[4 * jp + 2 * t + 1], ql[ks], kh[t][2], kh[t][3]);
                }
            }
        }

        // ---- masked online softmax ----
        unsigned long long mwA = mrowA[kt], mwB = mrowB[kt];
        float tmaxA = -1e30f, tmaxB = -1e30f;
#pragma unroll
        for (int j = 0; j < 8; j++) {
            int c0 = 8 * j + 2 * (lane & 3);
            sacc[j][0] = ((mwA >> c0) & 1ULL)       ? sacc[j][0] * 0.125f : -1e30f;
            sacc[j][1] = ((mwA >> (c0 + 1)) & 1ULL) ? sacc[j][1] * 0.125f : -1e30f;
            sacc[j][2] = ((mwB >> c0) & 1ULL)       ? sacc[j][2] * 0.125f : -1e30f;
            sacc[j][3] = ((mwB >> (c0 + 1)) & 1ULL) ? sacc[j][3] * 0.125f : -1e30f;
            tmaxA = fmaxf(tmaxA, fmaxf(sacc[j][0], sacc[j][1]));
            tmaxB = fmaxf(tmaxB, fmaxf(sacc[j][2], sacc[j][3]));
        }
        tmaxA = fmaxf(tmaxA, __shfl_xor_sync(0xffffffffu, tmaxA, 1));
        tmaxA = fmaxf(tmaxA, __shfl_xor_sync(0xffffffffu, tmaxA, 2));
        tmaxB = fmaxf(tmaxB, __shfl_xor_sync(0xffffffffu, tmaxB, 1));
        tmaxB = fmaxf(tmaxB, __shfl_xor_sync(0xffffffffu, tmaxB, 2));
        float nmA = fmaxf(mA, tmaxA), nmB = fmaxf(mB, tmaxB);
        float corrA = __expf(mA - nmA), corrB = __expf(mB - nmB);
        mA = nmA; mB = nmB;
        lA *= corrA; lB *= corrB;
#pragma unroll
        for (int j = 0; j < 8; j++) {
            oacc[j][0] *= corrA; oacc[j][1] *= corrA;
            oacc[j][2] *= corrB; oacc[j][3] *= corrB;
        }
        float psA = 0.f, psB = 0.f;
#pragma unroll
        for (int j = 0; j < 8; j++) {
            float p0 = (sacc[j][0] > -1e29f) ? __expf(sacc[j][0] - nmA) : 0.f;
            float p1 = (sacc[j][1] > -1e29f) ? __expf(sacc[j][1] - nmA) : 0.f;
            float p2 = (sacc[j][2] > -1e29f) ? __expf(sacc[j][2] - nmB) : 0.f;
            float p3 = (sacc[j][3] > -1e29f) ? __expf(sacc[j][3] - nmB) : 0.f;
            sacc[j][0] = p0; sacc[j][1] = p1; sacc[j][2] = p2; sacc[j][3] = p3;
            psA += p0 + p1; psB += p2 + p3;
        }
        psA += __shfl_xor_sync(0xffffffffu, psA, 1);
        psA += __shfl_xor_sync(0xffffffffu, psA, 2);
        psB += __shfl_xor_sync(0xffffffffu, psB, 1);
        psB += __shfl_xor_sync(0xffffffffu, psB, 2);
        lA += psA; lB += psB;

        // ---- PV: ctx += P(Vf), single fp16 term, term-major ----
#pragma unroll
        for (int ks = 0; ks < 4; ks++) {
            uint32_t pah[4];
            pah[0] = packh2(sacc[2 * ks][0],     sacc[2 * ks][1]);
            pah[1] = packh2(sacc[2 * ks][2],     sacc[2 * ks][3]);
            pah[2] = packh2(sacc[2 * ks + 1][0], sacc[2 * ks + 1][1]);
            pah[3] = packh2(sacc[2 * ks + 1][2], sacc[2 * ks + 1][3]);
#pragma unroll
            for (int dp = 0; dp < 2; dp++) {
                uint32_t vf[2][4];
#pragma unroll
                for (int t = 0; t < 2; t++) {
                    int kv = ks * 16 + (lane & 7) + ((lane & 8) ? 8 : 0);
                    int col = (2 * dp + t) * 16 + ((lane & 16) ? 8 : 0);
                    ldsm4t(vf[t], sVf + kv * QSTRIDE + col * 2);
                }
#pragma unroll
                for (int t = 0; t < 2; t++) {
                    mma16816h(oacc[4 * dp + 2 * t],     pah, vf[t][0], vf[t][1]);
                    mma16816h(oacc[4 * dp + 2 * t + 1], pah, vf[t][2], vf[t][3]);
                }
            }
        }
        __syncthreads();
    }

    // epilogue: normalize and write ctx directly as fp16 hi/lo
    float invA = (lA > 0.f) ? (1.f / lA) : 0.f;
    float invB = (lB > 0.f) ? (1.f / lB) : 0.f;
    size_t base0 = (size_t)(b * S_LEN + rA) * DMODEL + h * DKH;
    size_t base1 = base0 + (size_t)8 * DMODEL;
#pragma unroll
    for (int j = 0; j < 8; j++) {
        int col = 8 * j + 2 * (lane & 3);
        __half2 hh, ll;
        hsplit2(oacc[j][0] * invA, oacc[j][1] * invA, hh, ll);
        *(__half2*)(g_Ch + base0 + col) = hh;
        *(__half2*)(g_Cl + base0 + col) = ll;
        hsplit2(oacc[j][2] * invB, oacc[j][3] * invB, hh, ll);
        *(__half2*)(g_Ch + base1 + col) = hh;
        *(__half2*)(g_Cl + base1 + col) = ll;
    }
}

// ---------------- launch ----------------------------------------------------
extern "C" void kernel_launch(void* const* d_in, const int* in_sizes, int n_in,
                              void* d_out, int out_size) {
    const float* q    = (const float*)d_in[0];
    const float* k    = (const float*)d_in[1];
    const float* v    = (const float*)d_in[2];
    const int*   mask = (const int*)d_in[3];
    const float* Wq_w = (const float*)d_in[4];
    const float* Wq_b = (const float*)d_in[5];
    const float* Wk_w = (const float*)d_in[6];
    const float* Wk_b = (const float*)d_in[7];
    const float* Wv_w = (const float*)d_in[8];
    const float* Wv_b = (const float*)d_in[9];
    const float* Wo_w = (const float*)d_in[10];
    const float* Wo_b = (const float*)d_in[11];
    float* out = (float*)d_out;

    void *pXh, *pXl, *pWh, *pWl, *pQh, *pQl, *pKh, *pKl, *pVf, *pCh, *pCl;
    cudaGetSymbolAddress(&pXh, g_Xh);  cudaGetSymbolAddress(&pXl, g_Xl);
    cudaGetSymbolAddress(&pWh, g_Wh);  cudaGetSymbolAddress(&pWl, g_Wl);
    cudaGetSymbolAddress(&pQh, g_Qh);  cudaGetSymbolAddress(&pQl, g_Ql);
    cudaGetSymbolAddress(&pKh, g_Kh);  cudaGetSymbolAddress(&pKl, g_Kl);
    cudaGetSymbolAddress(&pVf, g_Vf);
    cudaGetSymbolAddress(&pCh, g_Ch);  cudaGetSymbolAddress(&pCl, g_Cl);

    cudaFuncSetAttribute(mma_gemm_kernel<0>,
                         cudaFuncAttributeMaxDynamicSharedMemorySize, GEMM_SMEM);
    cudaFuncSetAttribute(mma_gemm_kernel<1>,
                         cudaFuncAttributeMaxDynamicSharedMemorySize, GEMM_SMEM);
    cudaFuncSetAttribute(mma_gemm_kernel<2>,
                         cudaFuncAttributeMaxDynamicSharedMemorySize, GEMM_SMEM);
    cudaFuncSetAttribute(mma_attn_kernel,
                         cudaFuncAttributeMaxDynamicSharedMemorySize, ATT_SMEM);

    {
        int total_words = BATCH * S_LEN * MWORDS;
        int threads = total_words * 32;
        pack_mask_kernel<<<(threads + 255) / 256, 256>>>(mask);
    }

    const int nA4 = MTOT * DMODEL / 4;
    const int nW4 = DMODEL * DMODEL / 4;
    const size_t strideA = (size_t)MTOT * DMODEL / 2;
    const size_t strideW = (size_t)DMODEL * DMODEL / 2;

    cvt_split_batch<<<dim3((nA4 + 255) / 256, 3), 256>>>(
        (const float4*)q, (const float4*)k, (const float4*)v, (const float4*)v,
        (__half2*)pXh, (__half2*)pXl, strideA, nA4);
    cvt_split_batch<<<dim3((nW4 + 255) / 256, 4), 256>>>(
        (const float4*)Wq_w, (const float4*)Wk_w, (const float4*)Wv_w, (const float4*)Wo_w,
        (__half2*)pWh, (__half2*)pWl, strideW, nW4);

    dim3 gg(DMODEL / 128, MTOT / 128);
    const __half* Xh = (const __half*)pXh;
    const __half* Xl = (const __half*)pXl;
    const __half* Wh = (const __half*)pWh;
    const __half* Wl = (const __half*)pWl;
    const size_t aN = (size_t)MTOT * DMODEL;
    const size_t wN = (size_t)DMODEL * DMODEL;

    // Q projection -> fp16 hi/lo
    mma_gemm_kernel<1><<<gg, 256, GEMM_SMEM>>>(
        Xh, Xl, Wh, Wl, Wq_b,
        nullptr, (__half2*)pQh, (__half2*)pQl, nullptr, MTOT, DMODEL, DMODEL);
    // K projection -> fp16 hi/lo
    mma_gemm_kernel<1><<<gg, 256, GEMM_SMEM>>>(
        Xh + aN, Xl + aN, Wh + wN, Wl + wN, Wk_b,
        nullptr, (__half2*)pKh, (__half2*)pKl, nullptr, MTOT, DMODEL, DMODEL);
    // V projection -> fp16
    mma_gemm_kernel<2><<<gg, 256, GEMM_SMEM>>>(
        Xh + 2 * aN, Xl + 2 * aN, Wh + 2 * wN, Wl + 2 * wN, Wv_b,
        nullptr, nullptr, nullptr, (__half2*)pVf, MTOT, DMODEL, DMODEL);

    // attention -> ctx fp16 hi/lo
    mma_attn_kernel<<<dim3(S_LEN / 128, NHEAD, BATCH), 256, ATT_SMEM>>>();

    // O projection -> fp32 out
    mma_gemm_kernel<0><<<gg, 256, GEMM_SMEM>>>(
        (const __half*)pCh, (const __half*)pCl, Wh + 3 * wN, Wl + 3 * wN, Wo_b,
        out, nullptr, nullptr, nullptr, MTOT, DMODEL, DMODEL);
}

// round 16
// speedup vs baseline: 1.8609x; 1.2345x over previous
#include <cuda_runtime.h>
#include <cuda_bf16.h>
#include <cuda_fp16.h>
#include <cstdint>

#define S_LEN   2048
#define BATCH   2
#define DMODEL  1024
#define NHEAD   16
#define DKH     64
#define MTOT    (BATCH * S_LEN)
#define MWORDS  (S_LEN / 64)

// ---------------- scratch (static device globals) --------------------------
__device__ unsigned long long g_mbits[(size_t)BATCH * S_LEN * MWORDS];
__device__ __half g_Xh[3][(size_t)MTOT * DMODEL];
__device__ __half g_Xl[3][(size_t)MTOT * DMODEL];
__device__ __half g_Wh[4][(size_t)DMODEL * DMODEL];
__device__ __half g_Wl[4][(size_t)DMODEL * DMODEL];
__device__ __half g_Qf[(size_t)MTOT * DMODEL];          // Q single fp16
__device__ __half g_Kh[(size_t)MTOT * DMODEL];
__device__ __half g_Kl[(size_t)MTOT * DMODEL];
__device__ __half g_Vf[(size_t)MTOT * DMODEL];
__device__ __half g_Ch[(size_t)MTOT * DMODEL];
__device__ __half g_Cl[(size_t)MTOT * DMODEL];

// ---------------- helpers ---------------------------------------------------
__device__ __forceinline__ uint32_t smem_u32(const void* p) {
    uint32_t a;
    asm("{ .reg .u64 t; cvta.to.shared.u64 t, %1; cvt.u32.u64 %0, t; }"
        : "=r"(a) : "l"(p));
    return a;
}
__device__ __forceinline__ void ldsm4(uint32_t* r, uint32_t a) {
    asm volatile("ldmatrix.sync.aligned.m8n8.x4.shared.b16 {%0,%1,%2,%3}, [%4];"
                 : "=r"(r[0]), "=r"(r[1]), "=r"(r[2]), "=r"(r[3]) : "r"(a));
}
__device__ __forceinline__ void ldsm4t(uint32_t* r, uint32_t a) {
    asm volatile("ldmatrix.sync.aligned.m8n8.x4.trans.shared.b16 {%0,%1,%2,%3}, [%4];"
                 : "=r"(r[0]), "=r"(r[1]), "=r"(r[2]), "=r"(r[3]) : "r"(a));
}
__device__ __forceinline__ void mma16816h(float* d, const uint32_t* a,
                                          uint32_t b0, uint32_t b1) {
    asm volatile("mma.sync.aligned.m16n8k16.row.col.f32.f16.f16.f32 "
                 "{%0,%1,%2,%3}, {%4,%5,%6,%7}, {%8,%9}, {%0,%1,%2,%3};"
                 : "+f"(d[0]), "+f"(d[1]), "+f"(d[2]), "+f"(d[3])
                 : "r"(a[0]), "r"(a[1]), "r"(a[2]), "r"(a[3]), "r"(b0), "r"(b1));
}
__device__ __forceinline__ void cp16(uint32_t dst, const void* src) {
    asm volatile("cp.async.cg.shared.global [%0], [%1], 16;"
                 :: "r"(dst), "l"(src) : "memory");
}
__device__ __forceinline__ void cp_commit() {
    asm volatile("cp.async.commit_group;" ::: "memory");
}
template <int N> __device__ __forceinline__ void cp_wait() {
    asm volatile("cp.async.wait_group %0;" :: "n"(N) : "memory");
}
__device__ __forceinline__ uint32_t packh2(float a, float b) {
    __half2 h = __floats2half2_rn(a, b);
    return *reinterpret_cast<uint32_t*>(&h);
}
__device__ __forceinline__ void hsplit2(float a, float b, __half2& h, __half2& l) {
    h = __floats2half2_rn(a, b);
    float2 hf = __half22float2(h);
    l = __floats2half2_rn(a - hf.x, b - hf.y);
}

// ---------------- mask bit-packing -----------------------------------------
__global__ void pack_mask_kernel(const int* __restrict__ mask) {
    int gtid = blockIdx.x * blockDim.x + threadIdx.x;
    int w = gtid >> 5, lane = gtid & 31;
    int total_words = BATCH * S_LEN * MWORDS;
    if (w >= total_words) return;
    int row = w / MWORDS, j = w % MWORDS;
    size_t base = (size_t)row * S_LEN + (size_t)j * 64;
    unsigned b0 = __ballot_sync(0xffffffffu, mask[base + lane] != 0);
    unsigned b1 = __ballot_sync(0xffffffffu, mask[base + 32 + lane] != 0);
    if (lane == 0)
        g_mbits[w] = (unsigned long long)b0 | ((unsigned long long)b1 << 32);
}

// ---------------- batched fp32 -> fp16 hi/lo split --------------------------
__global__ __launch_bounds__(256) void cvt_split_batch(
    const float4* __restrict__ s0, const float4* __restrict__ s1,
    const float4* __restrict__ s2, const float4* __restrict__ s3,
    __half2* __restrict__ dh, __half2* __restrict__ dl,
    size_t stride_h2, int n4)
{
    int i = blockIdx.x * blockDim.x + threadIdx.x;
    if (i >= n4) return;
    int y = blockIdx.y;
    const float4* s = (y == 0) ? s0 : (y == 1) ? s1 : (y == 2) ? s2 : s3;
    float4 v = s[i];
    __half2 h0, l0, h1, l1;
    hsplit2(v.x, v.y, h0, l0);
    hsplit2(v.z, v.w, h1, l1);
    size_t o = (size_t)y * stride_h2 + 2 * (size_t)i;
    dh[o] = h0; dh[o + 1] = h1;
    dl[o] = l0; dl[o + 1] = l1;
}

// ---------------- mma.sync fp16 GEMM: Y = A @ B^T + bias --------------------
// CTA 128x128, 8 warps (4Mx2N), warp tile 32x64, K-chunk 32, double buffer.
// TERMS=3: Ah*Bh + Ah*Bl + Al*Bh (2^-22 grade). TERMS=2: Ah*(Bh+Bl) — for
// outputs that get rounded to single fp16 anyway; skips the Alo tile load.
#define ASTRIDE 80
#define ATILE   (128 * ASTRIDE)
#define GSTAGE  (4 * ATILE)
#define GEMM_SMEM (2 * GSTAGE)     // 81920

template <int MODE, int TERMS>   // MODE 0: fp32 out; 1: fp16 hi/lo; 2: fp16
__global__ __launch_bounds__(256, 2) void mma_gemm_kernel(
    const __half* __restrict__ Ahi, const __half* __restrict__ Alo,
    const __half* __restrict__ Bhi, const __half* __restrict__ Blo,
    const float* __restrict__ bias, float* __restrict__ Yf,
    __half2* __restrict__ Yhi, __half2* __restrict__ Ylo,
    __half2* __restrict__ Yh, int M, int N, int K)
{
    extern __shared__ char smem[];
    uint32_t sb = smem_u32(smem);
    int tid = threadIdx.x, lane = tid & 31, wid = tid >> 5;
    int bm = blockIdx.y * 128, bn = blockIdx.x * 128;
    int wmb = (wid >> 1) * 32, wnb = (wid & 1) * 64;

    float acc[2][8][4];
#pragma unroll
    for (int i = 0; i < 2; i++)
#pragma unroll
        for (int j = 0; j < 8; j++)
#pragma unroll
            for (int e = 0; e < 4; e++) acc[i][j][e] = 0.f;

#define GEMM_LOAD(c, st)                                                        \
    {                                                                           \
        uint32_t base = sb + (st) * GSTAGE;                                     \
        _Pragma("unroll")                                                       \
        for (int t = 0; t < 8; t++) {                                           \
            int tile = t >> 1;                                                  \
            if (TERMS == 2 && tile == 1) continue;                              \
            int w = (t & 1) * 256 + tid;                                        \
            int row = w >> 2, cu = w & 3;                                       \
            uint32_t dst = base + tile * ATILE + row * ASTRIDE + cu * 16;       \
            const __half* s;                                                    \
            if (tile == 0)      s = Ahi + (size_t)(bm + row) * K + (c) * 32 + cu * 8; \
            else if (tile == 1) s = Alo + (size_t)(bm + row) * K + (c) * 32 + cu * 8; \
            else if (tile == 2) s = Bhi + (size_t)(bn + row) * K + (c) * 32 + cu * 8; \
            else                s = Blo + (size_t)(bn + row) * K + (c) * 32 + cu * 8; \
            cp16(dst, s);                                                       \
        }                                                                       \
    }

    GEMM_LOAD(0, 0);
    cp_commit();

    int nch = K / 32;
    for (int c = 0; c < nch; c++) {
        if (c + 1 < nch) { GEMM_LOAD(c + 1, (c + 1) & 1); cp_commit(); cp_wait<1>(); }
        else cp_wait<0>();
        __syncthreads();

        uint32_t sAh = sb + (c & 1) * GSTAGE;
        uint32_t sAl = sAh + ATILE, sBh = sAh + 2 * ATILE, sBl = sAh + 3 * ATILE;
#pragma unroll
        for (int ks = 0; ks < 2; ks++) {
            uint32_t ah[2][4], al[2][4];
#pragma unroll
            for (int i = 0; i < 2; i++) {
                int row = wmb + i * 16 + (lane & 15);
                int col = ks * 16 + ((lane & 16) ? 8 : 0);
                ldsm4(ah[i], sAh + row * ASTRIDE + col * 2);
                if (TERMS == 3)
                    ldsm4(al[i], sAl + row * ASTRIDE + col * 2);
            }
#pragma unroll
            for (int jp = 0; jp < 2; jp++) {
                uint32_t bh[2][4], bl[2][4];
#pragma unroll
                for (int t = 0; t < 2; t++) {
                    int n = wnb + (2 * jp + t) * 16 + (lane & 7) + ((lane & 16) ? 8 : 0);
                    int col = ks * 16 + ((lane & 8) ? 8 : 0);
                    ldsm4(bh[t], sBh + n * ASTRIDE + col * 2);
                    ldsm4(bl[t], sBl + n * ASTRIDE + col * 2);
                }
                // term hh
#pragma unroll
                for (int i = 0; i < 2; i++)
#pragma unroll
                    for (int t = 0; t < 2; t++) {
                        mma16816h(acc[i][4 * jp + 2 * t],     ah[i], bh[t][0], bh[t][1]);
                        mma16816h(acc[i][4 * jp + 2 * t + 1], ah[i], bh[t][2], bh[t][3]);
                    }
                // term hl
#pragma unroll
                for (int i = 0; i < 2; i++)
#pragma unroll
                    for (int t = 0; t < 2; t++) {
                        mma16816h(acc[i][4 * jp + 2 * t],     ah[i], bl[t][0], bl[t][1]);
                        mma16816h(acc[i][4 * jp + 2 * t + 1], ah[i], bl[t][2], bl[t][3]);
                    }
                // term lh (full-precision mode only)
                if (TERMS == 3) {
#pragma unroll
                    for (int i = 0; i < 2; i++)
#pragma unroll
                        for (int t = 0; t < 2; t++) {
                            mma16816h(acc[i][4 * jp + 2 * t],     al[i], bh[t][0], bh[t][1]);
                            mma16816h(acc[i][4 * jp + 2 * t + 1], al[i], bh[t][2], bh[t][3]);
                        }
                }
            }
        }
        __syncthreads();
    }

#pragma unroll
    for (int i = 0; i < 2; i++) {
        int row = bm + wmb + i * 16 + (lane >> 2);
#pragma unroll
        for (int j = 0; j < 8; j++) {
            int col = bn + wnb + j * 8 + 2 * (lane & 3);
            float b0 = bias[col], b1 = bias[col + 1];
            float y0 = acc[i][j][0] + b0, y1 = acc[i][j][1] + b1;
            float y2 = acc[i][j][2] + b0, y3 = acc[i][j][3] + b1;
            size_t o0 = ((size_t)row * N + col);
            size_t o1 = ((size_t)(row + 8) * N + col);
            if (MODE == 0) {
                *(float2*)(Yf + o0) = make_float2(y0, y1);
                *(float2*)(Yf + o1) = make_float2(y2, y3);
            } else if (MODE == 1) {
                __half2 h, l;
                hsplit2(y0, y1, h, l);
                Yhi[o0 / 2] = h; Ylo[o0 / 2] = l;
                hsplit2(y2, y3, h, l);
                Yhi[o1 / 2] = h; Ylo[o1 / 2] = l;
            } else {
                Yh[o0 / 2] = __floats2half2_rn(y0, y1);
                Yh[o1 / 2] = __floats2half2_rn(y2, y3);
            }
        }
    }
}

// ---------------- mma.sync flash attention (all fp16) -----------------------
// CTA: 128 q-rows of one (b,h); 8 warps, warp = 16 q-rows; kv tiles of 64.
// QK: Qf x (Kh+Kl), 2 fp16 terms.  PV: single fp16 P x V.
#define QSTRIDE 144
#define QTILE   (128 * QSTRIDE)
#define KTILE   (64 * QSTRIDE)
#define KVSTAGE (3 * KTILE)                  // Kh, Kl, Vf
#define ATT_SMEM (QTILE + 2 * KVSTAGE)       // 73728

__global__ __launch_bounds__(256) void mma_attn_kernel()
{
    extern __shared__ char smem[];
    uint32_t sb = smem_u32(smem);
    int tid = threadIdx.x, lane = tid & 31, wid = tid >> 5;
    int qb = blockIdx.x * 128, h = blockIdx.y, b = blockIdx.z;
    uint32_t sQ = sb, sKV = sb + QTILE;
    int wq = wid * 16;

    // Q tile load (single fp16)
#pragma unroll
    for (int t = 0; t < 4; t++) {
        int w = t * 256 + tid;
        int row = w >> 3, cu = w & 7;
        const __half* s = g_Qf
            + (size_t)(b * S_LEN + qb + row) * DMODEL + h * DKH + cu * 8;
        cp16(sQ + row * QSTRIDE + cu * 16, s);
    }
#define ATT_LOADKV(kt, st)                                                      \
    {                                                                           \
        uint32_t base = sKV + (st) * KVSTAGE;                                   \
        _Pragma("unroll")                                                       \
        for (int t = 0; t < 6; t++) {                                           \
            int tile = t >> 1;                                                  \
            int w = (t & 1) * 256 + tid;                                        \
            int row = w >> 3, cu = w & 7;                                       \
            size_t g = (size_t)(b * S_LEN + (kt) * 64 + row) * DMODEL + h * DKH + cu * 8; \
            const void* s;                                                      \
            if (tile == 0)      s = (const void*)(g_Kh + g);                    \
            else if (tile == 1) s = (const void*)(g_Kl + g);                    \
            else                s = (const void*)(g_Vf + g);                    \
            cp16(base + tile * KTILE + row * QSTRIDE + cu * 16, s);             \
        }                                                                       \
    }
    ATT_LOADKV(0, 0);
    cp_commit();

    float oacc[8][4];
#pragma unroll
    for (int j = 0; j < 8; j++)
#pragma unroll
        for (int e = 0; e < 4; e++) oacc[j][e] = 0.f;
    float mA = -1e30f, mB = -1e30f, lA = 0.f, lB = 0.f;

    int rA = qb + wq + (lane >> 2);
    const unsigned long long* mrowA = g_mbits + (size_t)(b * S_LEN + rA) * MWORDS;
    const unsigned long long* mrowB = mrowA + (size_t)8 * MWORDS;

    uint32_t qf[4][4];

    for (int kt = 0; kt < 32; kt++) {
        if (kt + 1 < 32) { ATT_LOADKV(kt + 1, (kt + 1) & 1); cp_commit(); cp_wait<1>(); }
        else cp_wait<0>();
        __syncthreads();

        if (kt == 0) {
#pragma unroll
            for (int ks = 0; ks < 4; ks++) {
                int row = wq + (lane & 15);
                int col = ks * 16 + ((lane & 16) ? 8 : 0);
                ldsm4(qf[ks], sQ + row * QSTRIDE + col * 2);
            }
        }
        uint32_t sKh = sKV + (kt & 1) * KVSTAGE;
        uint32_t sKl = sKh + KTILE, sVf = sKh + 2 * KTILE;

        // ---- scores S = Qf (Kh+Kl)^T, 2 fp16 terms, term-major ----
        float sacc[8][4];
#pragma unroll
        for (int j = 0; j < 8; j++)
#pragma unroll
            for (int e = 0; e < 4; e++) sacc[j][e] = 0.f;
#pragma unroll
        for (int ks = 0; ks < 4; ks++) {
#pragma unroll
            for (int jp = 0; jp < 2; jp++) {
                uint32_t kh[2][4], kl[2][4];
#pragma unroll
                for (int t = 0; t < 2; t++) {
                    int n = (2 * jp + t) * 16 + (lane & 7) + ((lane & 16) ? 8 : 0);
                    int col = ks * 16 + ((lane & 8) ? 8 : 0);
                    ldsm4(kh[t], sKh + n * QSTRIDE + col * 2);
                    ldsm4(kl[t], sKl + n * QSTRIDE + col * 2);
                }
#pragma unroll
                for (int t = 0; t < 2; t++) {       // term hh
                    mma16816h(sacc[4 * jp + 2 * t],     qf[ks], kh[t][0], kh[t][1]);
                    mma16816h(sacc[4 * jp + 2 * t + 1], qf[ks], kh[t][2], kh[t][3]);
                }
#pragma unroll
                for (int t = 0; t < 2; t++) {       // term hl
                    mma16816h(sacc[4 * jp + 2 * t],     qf[ks], kl[t][0], kl[t][1]);
                    mma16816h(sacc[4 * jp + 2 * t + 1], qf[ks], kl[t][2], kl[t][3]);
                }
            }
        }

        // ---- masked online softmax ----
        unsigned long long mwA = mrowA[kt], mwB = mrowB[kt];
        float tmaxA = -1e30f, tmaxB = -1e30f;
#pragma unroll
        for (int j = 0; j < 8; j++) {
            int c0 = 8 * j + 2 * (lane & 3);
            sacc[j][0] = ((mwA >> c0) & 1ULL)       ? sacc[j][0] * 0.125f : -1e30f;
            sacc[j][1] = ((mwA >> (c0 + 1)) & 1ULL) ? sacc[j][1] * 0.125f : -1e30f;
            sacc[j][2] = ((mwB >> c0) & 1ULL)       ? sacc[j][2] * 0.125f : -1e30f;
            sacc[j][3] = ((mwB >> (c0 + 1)) & 1ULL) ? sacc[j][3] * 0.125f : -1e30f;
            tmaxA = fmaxf(tmaxA, fmaxf(sacc[j][0], sacc[j][1]));
            tmaxB = fmaxf(tmaxB, fmaxf(sacc[j][2], sacc[j][3]));
        }
        tmaxA = fmaxf(tmaxA, __shfl_xor_sync(0xffffffffu, tmaxA, 1));
        tmaxA = fmaxf(tmaxA, __shfl_xor_sync(0xffffffffu, tmaxA, 2));
        tmaxB = fmaxf(tmaxB, __shfl_xor_sync(0xffffffffu, tmaxB, 1));
        tmaxB = fmaxf(tmaxB, __shfl_xor_sync(0xffffffffu, tmaxB, 2));
        float nmA = fmaxf(mA, tmaxA), nmB = fmaxf(mB, tmaxB);
        float corrA = __expf(mA - nmA), corrB = __expf(mB - nmB);
        mA = nmA; mB = nmB;
        lA *= corrA; lB *= corrB;
#pragma unroll
        for (int j = 0; j < 8; j++) {
            oacc[j][0] *= corrA; oacc[j][1] *= corrA;
            oacc[j][2] *= corrB; oacc[j][3] *= corrB;
        }
        float psA = 0.f, psB = 0.f;
#pragma unroll
        for (int j = 0; j < 8; j++) {
            float p0 = (sacc[j][0] > -1e29f) ? __expf(sacc[j][0] - nmA) : 0.f;
            float p1 = (sacc[j][1] > -1e29f) ? __expf(sacc[j][1] - nmA) : 0.f;
            float p2 = (sacc[j][2] > -1e29f) ? __expf(sacc[j][2] - nmB) : 0.f;
            float p3 = (sacc[j][3] > -1e29f) ? __expf(sacc[j][3] - nmB) : 0.f;
            sacc[j][0] = p0; sacc[j][1] = p1; sacc[j][2] = p2; sacc[j][3] = p3;
            psA += p0 + p1; psB += p2 + p3;
        }
        psA += __shfl_xor_sync(0xffffffffu, psA, 1);
        psA += __shfl_xor_sync(0xffffffffu, psA, 2);
        psB += __shfl_xor_sync(0xffffffffu, psB, 1);
        psB += __shfl_xor_sync(0xffffffffu, psB, 2);
        lA += psA; lB += psB;

        // ---- PV: ctx += P(Vf), single fp16 term, term-major ----
#pragma unroll
        for (int ks = 0; ks < 4; ks++) {
            uint32_t pah[4];
            pah[0] = packh2(sacc[2 * ks][0],     sacc[2 * ks][1]);
            pah[1] = packh2(sacc[2 * ks][2],     sacc[2 * ks][3]);
            pah[2] = packh2(sacc[2 * ks + 1][0], sacc[2 * ks + 1][1]);
            pah[3] = packh2(sacc[2 * ks + 1][2], sacc[2 * ks + 1][3]);
#pragma unroll
            for (int dp = 0; dp < 2; dp++) {
                uint32_t vf[2][4];
#pragma unroll
                for (int t = 0; t < 2; t++) {
                    int kv = ks * 16 + (lane & 7) + ((lane & 8) ? 8 : 0);
                    int col = (2 * dp + t) * 16 + ((lane & 16) ? 8 : 0);
                    ldsm4t(vf[t], sVf + kv * QSTRIDE + col * 2);
                }
#pragma unroll
                for (int t = 0; t < 2; t++) {
                    mma16816h(oacc[4 * dp + 2 * t],     pah, vf[t][0], vf[t][1]);
                    mma16816h(oacc[4 * dp + 2 * t + 1], pah, vf[t][2], vf[t][3]);
                }
            }
        }
        __syncthreads();
    }

    // epilogue: normalize and write ctx directly as fp16 hi/lo
    float invA = (lA > 0.f) ? (1.f / lA) : 0.f;
    float invB = (lB > 0.f) ? (1.f / lB) : 0.f;
    size_t base0 = (size_t)(b * S_LEN + rA) * DMODEL + h * DKH;
    size_t base1 = base0 + (size_t)8 * DMODEL;
#pragma unroll
    for (int j = 0; j < 8; j++) {
        int col = 8 * j + 2 * (lane & 3);
        __half2 hh, ll;
        hsplit2(oacc[j][0] * invA, oacc[j][1] * invA, hh, ll);
        *(__half2*)(g_Ch + base0 + col) = hh;
        *(__half2*)(g_Cl + base0 + col) = ll;
        hsplit2(oacc[j][2] * invB, oacc[j][3] * invB, hh, ll);
        *(__half2*)(g_Ch + base1 + col) = hh;
        *(__half2*)(g_Cl + base1 + col) = ll;
    }
}

// ---------------- launch ----------------------------------------------------
extern "C" void kernel_launch(void* const* d_in, const int* in_sizes, int n_in,
                              void* d_out, int out_size) {
    const float* q    = (const float*)d_in[0];
    const float* k    = (const float*)d_in[1];
    const float* v    = (const float*)d_in[2];
    const int*   mask = (const int*)d_in[3];
    const float* Wq_w = (const float*)d_in[4];
    const float* Wq_b = (const float*)d_in[5];
    const float* Wk_w = (const float*)d_in[6];
    const float* Wk_b = (const float*)d_in[7];
    const float* Wv_w = (const float*)d_in[8];
    const float* Wv_b = (const float*)d_in[9];
    const float* Wo_w = (const float*)d_in[10];
    const float* Wo_b = (const float*)d_in[11];
    float* out = (float*)d_out;

    void *pXh, *pXl, *pWh, *pWl, *pQf, *pKh, *pKl, *pVf, *pCh, *pCl;
    cudaGetSymbolAddress(&pXh, g_Xh);  cudaGetSymbolAddress(&pXl, g_Xl);
    cudaGetSymbolAddress(&pWh, g_Wh);  cudaGetSymbolAddress(&pWl, g_Wl);
    cudaGetSymbolAddress(&pQf, g_Qf);
    cudaGetSymbolAddress(&pKh, g_Kh);  cudaGetSymbolAddress(&pKl, g_Kl);
    cudaGetSymbolAddress(&pVf, g_Vf);
    cudaGetSymbolAddress(&pCh, g_Ch);  cudaGetSymbolAddress(&pCl, g_Cl);

    cudaFuncSetAttribute((const void*)mma_gemm_kernel<0, 3>,
                         cudaFuncAttributeMaxDynamicSharedMemorySize, GEMM_SMEM);
    cudaFuncSetAttribute((const void*)mma_gemm_kernel<1, 3>,
                         cudaFuncAttributeMaxDynamicSharedMemorySize, GEMM_SMEM);
    cudaFuncSetAttribute((const void*)mma_gemm_kernel<2, 2>,
                         cudaFuncAttributeMaxDynamicSharedMemorySize, GEMM_SMEM);
    cudaFuncSetAttribute((const void*)mma_attn_kernel,
                         cudaFuncAttributeMaxDynamicSharedMemorySize, ATT_SMEM);

    {
        int total_words = BATCH * S_LEN * MWORDS;
        int threads = total_words * 32;
        pack_mask_kernel<<<(threads + 255) / 256, 256>>>(mask);
    }

    const int nA4 = MTOT * DMODEL / 4;
    const int nW4 = DMODEL * DMODEL / 4;
    const size_t strideA = (size_t)MTOT * DMODEL / 2;
    const size_t strideW = (size_t)DMODEL * DMODEL / 2;

    cvt_split_batch<<<dim3((nA4 + 255) / 256, 3), 256>>>(
        (const float4*)q, (const float4*)k, (const float4*)v, (const float4*)v,
        (__half2*)pXh, (__half2*)pXl, strideA, nA4);
    cvt_split_batch<<<dim3((nW4 + 255) / 256, 4), 256>>>(
        (const float4*)Wq_w, (const float4*)Wk_w, (const float4*)Wv_w, (const float4*)Wo_w,
        (__half2*)pWh, (__half2*)pWl, strideW, nW4);

    dim3 gg(DMODEL / 128, MTOT / 128);
    const __half* Xh = (const __half*)pXh;
    const __half* Xl = (const __half*)pXl;
    const __half* Wh = (const __half*)pWh;
    const __half* Wl = (const __half*)pWl;
    const size_t aN = (size_t)MTOT * DMODEL;
    const size_t wN = (size_t)DMODEL * DMODEL;

    // Q projection -> single fp16 (2-term: output rounds to fp16 anyway)
    mma_gemm_kernel<2, 2><<<gg, 256, GEMM_SMEM>>>(
        Xh, Xl, Wh, Wl, Wq_b,
        nullptr, nullptr, nullptr, (__half2*)pQf, MTOT, DMODEL, DMODEL);
    // K projection -> fp16 hi/lo (3-term: lo limb feeds the QK hl term)
    mma_gemm_kernel<1, 3><<<gg, 256, GEMM_SMEM>>>(
        Xh + aN, Xl + aN, Wh + wN, Wl + wN, Wk_b,
        nullptr, (__half2*)pKh, (__half2*)pKl, nullptr, MTOT, DMODEL, DMODEL);
    // V projection -> single fp16 (2-term)
    mma_gemm_kernel<2, 2><<<gg, 256, GEMM_SMEM>>>(
        Xh + 2 * aN, Xl + 2 * aN, Wh + 2 * wN, Wl + 2 * wN, Wv_b,
        nullptr, nullptr, nullptr, (__half2*)pVf, MTOT, DMODEL, DMODEL);

    // attention -> ctx fp16 hi/lo
    mma_attn_kernel<<<dim3(S_LEN / 128, NHEAD, BATCH), 256, ATT_SMEM>>>();

    // O projection -> fp32 out (3-term: final output precision)
    mma_gemm_kernel<0, 3><<<gg, 256, GEMM_SMEM>>>(
        (const __half*)pCh, (const __half*)pCl, Wh + 3 * wN, Wl + 3 * wN, Wo_b,
        out, nullptr, nullptr, nullptr, MTOT, DMODEL, DMODEL);
}

// round 17
// speedup vs baseline: 2.1954x; 1.1797x over previous
#include <cuda_runtime.h>
#include <cuda_bf16.h>
#include <cuda_fp16.h>
#include <cstdint>

#define S_LEN   2048
#define BATCH   2
#define DMODEL  1024
#define NHEAD   16
#define DKH     64
#define MTOT    (BATCH * S_LEN)
#define MWORDS  (S_LEN / 64)

// ---------------- scratch (static device globals) --------------------------
__device__ unsigned long long g_mbits[(size_t)BATCH * S_LEN * MWORDS];
__device__ __half g_Xh[3][(size_t)MTOT * DMODEL];
__device__ __half g_Xl[3][(size_t)MTOT * DMODEL];
__device__ __half g_Wh[4][(size_t)DMODEL * DMODEL];
__device__ __half g_Wl[4][(size_t)DMODEL * DMODEL];
__device__ __half g_Qf[(size_t)MTOT * DMODEL];   // Q single fp16
__device__ __half g_Kf[(size_t)MTOT * DMODEL];   // K single fp16
__device__ __half g_Vf[(size_t)MTOT * DMODEL];   // V single fp16
__device__ __half g_Cf[(size_t)MTOT * DMODEL];   // ctx single fp16

// ---------------- helpers ---------------------------------------------------
__device__ __forceinline__ uint32_t smem_u32(const void* p) {
    uint32_t a;
    asm("{ .reg .u64 t; cvta.to.shared.u64 t, %1; cvt.u32.u64 %0, t; }"
        : "=r"(a) : "l"(p));
    return a;
}
__device__ __forceinline__ void ldsm4(uint32_t* r, uint32_t a) {
    asm volatile("ldmatrix.sync.aligned.m8n8.x4.shared.b16 {%0,%1,%2,%3}, [%4];"
                 : "=r"(r[0]), "=r"(r[1]), "=r"(r[2]), "=r"(r[3]) : "r"(a));
}
__device__ __forceinline__ void ldsm4t(uint32_t* r, uint32_t a) {
    asm volatile("ldmatrix.sync.aligned.m8n8.x4.trans.shared.b16 {%0,%1,%2,%3}, [%4];"
                 : "=r"(r[0]), "=r"(r[1]), "=r"(r[2]), "=r"(r[3]) : "r"(a));
}
__device__ __forceinline__ void mma16816h(float* d, const uint32_t* a,
                                          uint32_t b0, uint32_t b1) {
    asm volatile("mma.sync.aligned.m16n8k16.row.col.f32.f16.f16.f32 "
                 "{%0,%1,%2,%3}, {%4,%5,%6,%7}, {%8,%9}, {%0,%1,%2,%3};"
                 : "+f"(d[0]), "+f"(d[1]), "+f"(d[2]), "+f"(d[3])
                 : "r"(a[0]), "r"(a[1]), "r"(a[2]), "r"(a[3]), "r"(b0), "r"(b1));
}
__device__ __forceinline__ void cp16(uint32_t dst, const void* src) {
    asm volatile("cp.async.cg.shared.global [%0], [%1], 16;"
                 :: "r"(dst), "l"(src) : "memory");
}
__device__ __forceinline__ void cp_commit() {
    asm volatile("cp.async.commit_group;" ::: "memory");
}
template <int N> __device__ __forceinline__ void cp_wait() {
    asm volatile("cp.async.wait_group %0;" :: "n"(N) : "memory");
}
__device__ __forceinline__ uint32_t packh2(float a, float b) {
    __half2 h = __floats2half2_rn(a, b);
    return *reinterpret_cast<uint32_t*>(&h);
}
__device__ __forceinline__ void hsplit2(float a, float b, __half2& h, __half2& l) {
    h = __floats2half2_rn(a, b);
    float2 hf = __half22float2(h);
    l = __floats2half2_rn(a - hf.x, b - hf.y);
}

// ---------------- mask bit-packing -----------------------------------------
__global__ void pack_mask_kernel(const int* __restrict__ mask) {
    int gtid = blockIdx.x * blockDim.x + threadIdx.x;
    int w = gtid >> 5, lane = gtid & 31;
    int total_words = BATCH * S_LEN * MWORDS;
    if (w >= total_words) return;
    int row = w / MWORDS, j = w % MWORDS;
    size_t base = (size_t)row * S_LEN + (size_t)j * 64;
    unsigned b0 = __ballot_sync(0xffffffffu, mask[base + lane] != 0);
    unsigned b1 = __ballot_sync(0xffffffffu, mask[base + 32 + lane] != 0);
    if (lane == 0)
        g_mbits[w] = (unsigned long long)b0 | ((unsigned long long)b1 << 32);
}

// ---------------- batched fp32 -> fp16 hi/lo split --------------------------
__global__ __launch_bounds__(256) void cvt_split_batch(
    const float4* __restrict__ s0, const float4* __restrict__ s1,
    const float4* __restrict__ s2, const float4* __restrict__ s3,
    __half2* __restrict__ dh, __half2* __restrict__ dl,
    size_t stride_h2, int n4)
{
    int i = blockIdx.x * blockDim.x + threadIdx.x;
    if (i >= n4) return;
    int y = blockIdx.y;
    const float4* s = (y == 0) ? s0 : (y == 1) ? s1 : (y == 2) ? s2 : s3;
    float4 v = s[i];
    __half2 h0, l0, h1, l1;
    hsplit2(v.x, v.y, h0, l0);
    hsplit2(v.z, v.w, h1, l1);
    size_t o = (size_t)y * stride_h2 + 2 * (size_t)i;
    dh[o] = h0; dh[o + 1] = h1;
    dl[o] = l0; dl[o + 1] = l1;
}

// ---------------- mma.sync fp16 GEMM: Y = A @ B^T + bias --------------------
// CTA 128x128, 8 warps (4Mx2N), warp tile 32x64, K-chunk 32, double buffer.
// TERMS=3: Ah*Bh + Ah*Bl + Al*Bh.  TERMS=2: Ah*(Bh+Bl) (A rounded to fp16).
#define ASTRIDE 80
#define ATILE   (128 * ASTRIDE)
#define GSTAGE  (4 * ATILE)
#define GEMM_SMEM (2 * GSTAGE)     // 81920

template <int MODE, int TERMS>   // MODE 0: fp32 out; 2: fp16 out
__global__ __launch_bounds__(256, 2) void mma_gemm_kernel(
    const __half* __restrict__ Ahi, const __half* __restrict__ Alo,
    const __half* __restrict__ Bhi, const __half* __restrict__ Blo,
    const float* __restrict__ bias, float* __restrict__ Yf,
    __half2* __restrict__ Yh, int M, int N, int K)
{
    extern __shared__ char smem[];
    uint32_t sb = smem_u32(smem);
    int tid = threadIdx.x, lane = tid & 31, wid = tid >> 5;
    int bm = blockIdx.y * 128, bn = blockIdx.x * 128;
    int wmb = (wid >> 1) * 32, wnb = (wid & 1) * 64;

    float acc[2][8][4];
#pragma unroll
    for (int i = 0; i < 2; i++)
#pragma unroll
        for (int j = 0; j < 8; j++)
#pragma unroll
            for (int e = 0; e < 4; e++) acc[i][j][e] = 0.f;

#define GEMM_LOAD(c, st)                                                        \
    {                                                                           \
        uint32_t base = sb + (st) * GSTAGE;                                     \
        _Pragma("unroll")                                                       \
        for (int t = 0; t < 8; t++) {                                           \
            int tile = t >> 1;                                                  \
            if (TERMS == 2 && tile == 1) continue;                              \
            int w = (t & 1) * 256 + tid;                                        \
            int row = w >> 2, cu = w & 3;                                       \
            uint32_t dst = base + tile * ATILE + row * ASTRIDE + cu * 16;       \
            const __half* s;                                                    \
            if (tile == 0)      s = Ahi + (size_t)(bm + row) * K + (c) * 32 + cu * 8; \
            else if (tile == 1) s = Alo + (size_t)(bm + row) * K + (c) * 32 + cu * 8; \
            else if (tile == 2) s = Bhi + (size_t)(bn + row) * K + (c) * 32 + cu * 8; \
            else                s = Blo + (size_t)(bn + row) * K + (c) * 32 + cu * 8; \
            cp16(dst, s);                                                       \
        }                                                                       \
    }

    GEMM_LOAD(0, 0);
    cp_commit();

    int nch = K / 32;
    for (int c = 0; c < nch; c++) {
        if (c + 1 < nch) { GEMM_LOAD(c + 1, (c + 1) & 1); cp_commit(); cp_wait<1>(); }
        else cp_wait<0>();
        __syncthreads();

        uint32_t sAh = sb + (c & 1) * GSTAGE;
        uint32_t sAl = sAh + ATILE, sBh = sAh + 2 * ATILE, sBl = sAh + 3 * ATILE;
#pragma unroll
        for (int ks = 0; ks < 2; ks++) {
            uint32_t ah[2][4], al[2][4];
#pragma unroll
            for (int i = 0; i < 2; i++) {
                int row = wmb + i * 16 + (lane & 15);
                int col = ks * 16 + ((lane & 16) ? 8 : 0);
                ldsm4(ah[i], sAh + row * ASTRIDE + col * 2);
                if (TERMS == 3)
                    ldsm4(al[i], sAl + row * ASTRIDE + col * 2);
            }
#pragma unroll
            for (int jp = 0; jp < 2; jp++) {
                uint32_t bh[2][4], bl[2][4];
#pragma unroll
                for (int t = 0; t < 2; t++) {
                    int n = wnb + (2 * jp + t) * 16 + (lane & 7) + ((lane & 16) ? 8 : 0);
                    int col = ks * 16 + ((lane & 8) ? 8 : 0);
                    ldsm4(bh[t], sBh + n * ASTRIDE + col * 2);
                    ldsm4(bl[t], sBl + n * ASTRIDE + col * 2);
                }
                // term hh
#pragma unroll
                for (int i = 0; i < 2; i++)
#pragma unroll
                    for (int t = 0; t < 2; t++) {
                        mma16816h(acc[i][4 * jp + 2 * t],     ah[i], bh[t][0], bh[t][1]);
                        mma16816h(acc[i][4 * jp + 2 * t + 1], ah[i], bh[t][2], bh[t][3]);
                    }
                // term hl
#pragma unroll
                for (int i = 0; i < 2; i++)
#pragma unroll
                    for (int t = 0; t < 2; t++) {
                        mma16816h(acc[i][4 * jp + 2 * t],     ah[i], bl[t][0], bl[t][1]);
                        mma16816h(acc[i][4 * jp + 2 * t + 1], ah[i], bl[t][2], bl[t][3]);
                    }
                // term lh (full-precision mode only)
                if (TERMS == 3) {
#pragma unroll
                    for (int i = 0; i < 2; i++)
#pragma unroll
                        for (int t = 0; t < 2; t++) {
                            mma16816h(acc[i][4 * jp + 2 * t],     al[i], bh[t][0], bh[t][1]);
                            mma16816h(acc[i][4 * jp + 2 * t + 1], al[i], bh[t][2], bh[t][3]);
                        }
                }
            }
        }
        __syncthreads();
    }

#pragma unroll
    for (int i = 0; i < 2; i++) {
        int row = bm + wmb + i * 16 + (lane >> 2);
#pragma unroll
        for (int j = 0; j < 8; j++) {
            int col = bn + wnb + j * 8 + 2 * (lane & 3);
            float b0 = bias[col], b1 = bias[col + 1];
            float y0 = acc[i][j][0] + b0, y1 = acc[i][j][1] + b1;
            float y2 = acc[i][j][2] + b0, y3 = acc[i][j][3] + b1;
            size_t o0 = ((size_t)row * N + col);
            size_t o1 = ((size_t)(row + 8) * N + col);
            if (MODE == 0) {
                *(float2*)(Yf + o0) = make_float2(y0, y1);
                *(float2*)(Yf + o1) = make_float2(y2, y3);
            } else {
                Yh[o0 / 2] = __floats2half2_rn(y0, y1);
                Yh[o1 / 2] = __floats2half2_rn(y2, y3);
            }
        }
    }
}

// ---------------- mma.sync flash attention (all fp16) -----------------------
// CTA: 128 q-rows of one (b,h); 8 warps, warp = 16 q-rows; kv tiles of 64.
// QK: single fp16 term Qf x Kf.  PV: single fp16 P x V.
#define QSTRIDE 144
#define QTILE   (128 * QSTRIDE)
#define KTILE   (64 * QSTRIDE)
#define KVSTAGE (2 * KTILE)                  // Kf, Vf
#define ATT_SMEM (QTILE + 2 * KVSTAGE)       // 55296

__global__ __launch_bounds__(256) void mma_attn_kernel()
{
    extern __shared__ char smem[];
    uint32_t sb = smem_u32(smem);
    int tid = threadIdx.x, lane = tid & 31, wid = tid >> 5;
    int qb = blockIdx.x * 128, h = blockIdx.y, b = blockIdx.z;
    uint32_t sQ = sb, sKV = sb + QTILE;
    int wq = wid * 16;

    // Q tile load (single fp16)
#pragma unroll
    for (int t = 0; t < 4; t++) {
        int w = t * 256 + tid;
        int row = w >> 3, cu = w & 7;
        const __half* s = g_Qf
            + (size_t)(b * S_LEN + qb + row) * DMODEL + h * DKH + cu * 8;
        cp16(sQ + row * QSTRIDE + cu * 16, s);
    }
#define ATT_LOADKV(kt, st)                                                      \
    {                                                                           \
        uint32_t base = sKV + (st) * KVSTAGE;                                   \
        _Pragma("unroll")                                                       \
        for (int t = 0; t < 4; t++) {                                           \
            int tile = t >> 1;                                                  \
            int w = (t & 1) * 256 + tid;                                        \
            int row = w >> 3, cu = w & 7;                                       \
            size_t g = (size_t)(b * S_LEN + (kt) * 64 + row) * DMODEL + h * DKH + cu * 8; \
            const void* s = (tile == 0) ? (const void*)(g_Kf + g)               \
                                        : (const void*)(g_Vf + g);              \
            cp16(base + tile * KTILE + row * QSTRIDE + cu * 16, s);             \
        }                                                                       \
    }
    ATT_LOADKV(0, 0);
    cp_commit();

    float oacc[8][4];
#pragma unroll
    for (int j = 0; j < 8; j++)
#pragma unroll
        for (int e = 0; e < 4; e++) oacc[j][e] = 0.f;
    float mA = -1e30f, mB = -1e30f, lA = 0.f, lB = 0.f;

    int rA = qb + wq + (lane >> 2);
    const unsigned long long* mrowA = g_mbits + (size_t)(b * S_LEN + rA) * MWORDS;
    const unsigned long long* mrowB = mrowA + (size_t)8 * MWORDS;

    uint32_t qf[4][4];

    for (int kt = 0; kt < 32; kt++) {
        if (kt + 1 < 32) { ATT_LOADKV(kt + 1, (kt + 1) & 1); cp_commit(); cp_wait<1>(); }
        else cp_wait<0>();
        __syncthreads();

        if (kt == 0) {
#pragma unroll
            for (int ks = 0; ks < 4; ks++) {
                int row = wq + (lane & 15);
                int col = ks * 16 + ((lane & 16) ? 8 : 0);
                ldsm4(qf[ks], sQ + row * QSTRIDE + col * 2);
            }
        }
        uint32_t sKf = sKV + (kt & 1) * KVSTAGE;
        uint32_t sVf = sKf + KTILE;

        // ---- scores S = Qf Kf^T, single fp16 term ----
        float sacc[8][4];
#pragma unroll
        for (int j = 0; j < 8; j++)
#pragma unroll
            for (int e = 0; e < 4; e++) sacc[j][e] = 0.f;
#pragma unroll
        for (int ks = 0; ks < 4; ks++) {
#pragma unroll
            for (int jp = 0; jp < 2; jp++) {
                uint32_t kf[2][4];
#pragma unroll
                for (int t = 0; t < 2; t++) {
                    int n = (2 * jp + t) * 16 + (lane & 7) + ((lane & 16) ? 8 : 0);
                    int col = ks * 16 + ((lane & 8) ? 8 : 0);
                    ldsm4(kf[t], sKf + n * QSTRIDE + col * 2);
                }
#pragma unroll
                for (int t = 0; t < 2; t++) {
                    mma16816h(sacc[4 * jp + 2 * t],     qf[ks], kf[t][0], kf[t][1]);
                    mma16816h(sacc[4 * jp + 2 * t + 1], qf[ks], kf[t][2], kf[t][3]);
                }
            }
        }

        // ---- masked online softmax ----
        unsigned long long mwA = mrowA[kt], mwB = mrowB[kt];
        float tmaxA = -1e30f, tmaxB = -1e30f;
#pragma unroll
        for (int j = 0; j < 8; j++) {
            int c0 = 8 * j + 2 * (lane & 3);
            sacc[j][0] = ((mwA >> c0) & 1ULL)       ? sacc[j][0] * 0.125f : -1e30f;
            sacc[j][1] = ((mwA >> (c0 + 1)) & 1ULL) ? sacc[j][1] * 0.125f : -1e30f;
            sacc[j][2] = ((mwB >> c0) & 1ULL)       ? sacc[j][2] * 0.125f : -1e30f;
            sacc[j][3] = ((mwB >> (c0 + 1)) & 1ULL) ? sacc[j][3] * 0.125f : -1e30f;
            tmaxA = fmaxf(tmaxA, fmaxf(sacc[j][0], sacc[j][1]));
            tmaxB = fmaxf(tmaxB, fmaxf(sacc[j][2], sacc[j][3]));
        }
        tmaxA = fmaxf(tmaxA, __shfl_xor_sync(0xffffffffu, tmaxA, 1));
        tmaxA = fmaxf(tmaxA, __shfl_xor_sync(0xffffffffu, tmaxA, 2));
        tmaxB = fmaxf(tmaxB, __shfl_xor_sync(0xffffffffu, tmaxB, 1));
        tmaxB = fmaxf(tmaxB, __shfl_xor_sync(0xffffffffu, tmaxB, 2));
        float nmA = fmaxf(mA, tmaxA), nmB = fmaxf(mB, tmaxB);
        float corrA = __expf(mA - nmA), corrB = __expf(mB - nmB);
        mA = nmA; mB = nmB;
        lA *= corrA; lB *= corrB;
#pragma unroll
        for (int j = 0; j < 8; j++) {
            oacc[j][0] *= corrA; oacc[j][1] *= corrA;
            oacc[j][2] *= corrB; oacc[j][3] *= corrB;
        }
        float psA = 0.f, psB = 0.f;
#pragma unroll
        for (int j = 0; j < 8; j++) {
            float p0 = (sacc[j][0] > -1e29f) ? __expf(sacc[j][0] - nmA) : 0.f;
            float p1 = (sacc[j][1] > -1e29f) ? __expf(sacc[j][1] - nmA) : 0.f;
            float p2 = (sacc[j][2] > -1e29f) ? __expf(sacc[j][2] - nmB) : 0.f;
            float p3 = (sacc[j][3] > -1e29f) ? __expf(sacc[j][3] - nmB) : 0.f;
            sacc[j][0] = p0; sacc[j][1] = p1; sacc[j][2] = p2; sacc[j][3] = p3;
            psA += p0 + p1; psB += p2 + p3;
        }
        psA += __shfl_xor_sync(0xffffffffu, psA, 1);
        psA += __shfl_xor_sync(0xffffffffu, psA, 2);
        psB += __shfl_xor_sync(0xffffffffu, psB, 1);
        psB += __shfl_xor_sync(0xffffffffu, psB, 2);
        lA += psA; lB += psB;

        // ---- PV: ctx += P(Vf), single fp16 term ----
#pragma unroll
        for (int ks = 0; ks < 4; ks++) {
            uint32_t pah[4];
            pah[0] = packh2(sacc[2 * ks][0],     sacc[2 * ks][1]);
            pah[1] = packh2(sacc[2 * ks][2],     sacc[2 * ks][3]);
            pah[2] = packh2(sacc[2 * ks + 1][0], sacc[2 * ks + 1][1]);
            pah[3] = packh2(sacc[2 * ks + 1][2], sacc[2 * ks + 1][3]);
#pragma unroll
            for (int dp = 0; dp < 2; dp++) {
                uint32_t vf[2][4];
#pragma unroll
                for (int t = 0; t < 2; t++) {
                    int kv = ks * 16 + (lane & 7) + ((lane & 8) ? 8 : 0);
                    int col = (2 * dp + t) * 16 + ((lane & 16) ? 8 : 0);
                    ldsm4t(vf[t], sVf + kv * QSTRIDE + col * 2);
                }
#pragma unroll
                for (int t = 0; t < 2; t++) {
                    mma16816h(oacc[4 * dp + 2 * t],     pah, vf[t][0], vf[t][1]);
                    mma16816h(oacc[4 * dp + 2 * t + 1], pah, vf[t][2], vf[t][3]);
                }
            }
        }
        __syncthreads();
    }

    // epilogue: normalize and write ctx as single fp16
    float invA = (lA > 0.f) ? (1.f / lA) : 0.f;
    float invB = (lB > 0.f) ? (1.f / lB) : 0.f;
    size_t base0 = (size_t)(b * S_LEN + rA) * DMODEL + h * DKH;
    size_t base1 = base0 + (size_t)8 * DMODEL;
#pragma unroll
    for (int j = 0; j < 8; j++) {
        int col = 8 * j + 2 * (lane & 3);
        *(__half2*)(g_Cf + base0 + col) =
            __floats2half2_rn(oacc[j][0] * invA, oacc[j][1] * invA);
        *(__half2*)(g_Cf + base1 + col) =
            __floats2half2_rn(oacc[j][2] * invB, oacc[j][3] * invB);
    }
}

// ---------------- launch ----------------------------------------------------
extern "C" void kernel_launch(void* const* d_in, const int* in_sizes, int n_in,
                              void* d_out, int out_size) {
    const float* q    = (const float*)d_in[0];
    const float* k    = (const float*)d_in[1];
    const float* v    = (const float*)d_in[2];
    const int*   mask = (const int*)d_in[3];
    const float* Wq_w = (const float*)d_in[4];
    const float* Wq_b = (const float*)d_in[5];
    const float* Wk_w = (const float*)d_in[6];
    const float* Wk_b = (const float*)d_in[7];
    const float* Wv_w = (const float*)d_in[8];
    const float* Wv_b = (const float*)d_in[9];
    const float* Wo_w = (const float*)d_in[10];
    const float* Wo_b = (const float*)d_in[11];
    float* out = (float*)d_out;

    void *pXh, *pXl, *pWh, *pWl, *pQf, *pKf, *pVf, *pCf;
    cudaGetSymbolAddress(&pXh, g_Xh);  cudaGetSymbolAddress(&pXl, g_Xl);
    cudaGetSymbolAddress(&pWh, g_Wh);  cudaGetSymbolAddress(&pWl, g_Wl);
    cudaGetSymbolAddress(&pQf, g_Qf);  cudaGetSymbolAddress(&pKf, g_Kf);
    cudaGetSymbolAddress(&pVf, g_Vf);  cudaGetSymbolAddress(&pCf, g_Cf);

    cudaFuncSetAttribute((const void*)mma_gemm_kernel<0, 2>,
                         cudaFuncAttributeMaxDynamicSharedMemorySize, GEMM_SMEM);
    cudaFuncSetAttribute((const void*)mma_gemm_kernel<2, 2>,
                         cudaFuncAttributeMaxDynamicSharedMemorySize, GEMM_SMEM);
    cudaFuncSetAttribute((const void*)mma_attn_kernel,
                         cudaFuncAttributeMaxDynamicSharedMemorySize, ATT_SMEM);

    {
        int total_words = BATCH * S_LEN * MWORDS;
        int threads = total_words * 32;
        pack_mask_kernel<<<(threads + 255) / 256, 256>>>(mask);
    }

    const int nA4 = MTOT * DMODEL / 4;
    const int nW4 = DMODEL * DMODEL / 4;
    const size_t strideA = (size_t)MTOT * DMODEL / 2;
    const size_t strideW = (size_t)DMODEL * DMODEL / 2;

    cvt_split_batch<<<dim3((nA4 + 255) / 256, 3), 256>>>(
        (const float4*)q, (const float4*)k, (const float4*)v, (const float4*)v,
        (__half2*)pXh, (__half2*)pXl, strideA, nA4);
    cvt_split_batch<<<dim3((nW4 + 255) / 256, 4), 256>>>(
        (const float4*)Wq_w, (const float4*)Wk_w, (const float4*)Wv_w, (const float4*)Wo_w,
        (__half2*)pWh, (__half2*)pWl, strideW, nW4);

    dim3 gg(DMODEL / 128, MTOT / 128);
    const __half* Xh = (const __half*)pXh;
    const __half* Xl = (const __half*)pXl;
    const __half* Wh = (const __half*)pWh;
    const __half* Wl = (const __half*)pWl;
    const size_t aN = (size_t)MTOT * DMODEL;
    const size_t wN = (size_t)DMODEL * DMODEL;

    // Q projection -> single fp16 (2-term)
    mma_gemm_kernel<2, 2><<<gg, 256, GEMM_SMEM>>>(
        Xh, Xl, Wh, Wl, Wq_b,
        nullptr, (__half2*)pQf, MTOT, DMODEL, DMODEL);
    // K projection -> single fp16 (2-term)
    mma_gemm_kernel<2, 2><<<gg, 256, GEMM_SMEM>>>(
        Xh + aN, Xl + aN, Wh + wN, Wl + wN, Wk_b,
        nullptr, (__half2*)pKf, MTOT, DMODEL, DMODEL);
    // V projection -> single fp16 (2-term)
    mma_gemm_kernel<2, 2><<<gg, 256, GEMM_SMEM>>>(
        Xh + 2 * aN, Xl + 2 * aN, Wh + 2 * wN, Wl + 2 * wN, Wv_b,
        nullptr, (__half2*)pVf, MTOT, DMODEL, DMODEL);

    // attention -> ctx single fp16
    mma_attn_kernel<<<dim3(S_LEN / 128, NHEAD, BATCH), 256, ATT_SMEM>>>();

    // O projection -> fp32 out (2-term: ctx already fp16-rounded)
    mma_gemm_kernel<0, 2><<<gg, 256, GEMM_SMEM>>>(
        (const __half*)pCf, nullptr, Wh + 3 * wN, Wl + 3 * wN, Wo_b,
        out, nullptr, MTOT, DMODEL, DMODEL);
}